// round 6
// baseline (speedup 1.0000x reference)
#include <cuda_runtime.h>
#include <cuda_bf16.h>
#include <cstdint>

#define N_NODES 100000
#define E_MAX   1600000
#define NPART   98          // ceil(100000/1024)

// ---------------- device scratch (static; no dynamic allocation) ----------------
__device__ int   g_is64;
__device__ int   g_deg[N_NODES];
__device__ int   g_offs[N_NODES + 1];
__device__ int   g_cursor[N_NODES];
__device__ int   g_part[NPART];
__device__ int   g_dst32[E_MAX];
__device__ int   g_src_sorted[E_MAX];
// bf16 split A operands (per layer: A = [agg | x_or_h])
__device__ __nv_bfloat16 g_a1h[(size_t)N_NODES * 128];
__device__ __nv_bfloat16 g_a1l[(size_t)N_NODES * 128];
__device__ __nv_bfloat16 g_a2h[(size_t)N_NODES * 256];
__device__ __nv_bfloat16 g_a2l[(size_t)N_NODES * 256];
__device__ __nv_bfloat16 g_w1h[128 * 128];
__device__ __nv_bfloat16 g_w1l[128 * 128];
__device__ __nv_bfloat16 g_w2h[128 * 256];
__device__ __nv_bfloat16 g_w2l[128 * 256];

// ==================== PTX helpers (family-portable) ====================
__device__ __forceinline__ uint32_t smem_u32(const void* p) {
    uint32_t a;
    asm("{ .reg .u64 t; cvta.to.shared.u64 t, %1; cvt.u32.u64 %0, t; }" : "=r"(a) : "l"(p));
    return a;
}
#define LDSM_X4(r0, r1, r2, r3, addr)                                           \
    asm volatile("ldmatrix.sync.aligned.m8n8.x4.shared.b16 {%0,%1,%2,%3}, [%4];" \
                 : "=r"(r0), "=r"(r1), "=r"(r2), "=r"(r3) : "r"(addr))
#define MMA16816(c, a, b)                                                        \
    asm volatile("mma.sync.aligned.m16n8k16.row.col.f32.bf16.bf16.f32 "          \
                 "{%0,%1,%2,%3}, {%4,%5,%6,%7}, {%8,%9}, {%0,%1,%2,%3};"         \
                 : "+f"((c)[0]), "+f"((c)[1]), "+f"((c)[2]), "+f"((c)[3])        \
                 : "r"((a)[0]), "r"((a)[1]), "r"((a)[2]), "r"((a)[3]),           \
                   "r"((b)[0]), "r"((b)[1]))
__device__ __forceinline__ void cp16(uint32_t dst, const void* src) {
    asm volatile("cp.async.cg.shared.global [%0], [%1], 16;" :: "r"(dst), "l"(src));
}
#define CP_COMMIT() asm volatile("cp.async.commit_group;" ::: "memory")
#define CP_WAIT1()  asm volatile("cp.async.wait_group 1;" ::: "memory")
#define CP_WAIT0()  asm volatile("cp.async.wait_group 0;" ::: "memory")

__device__ __forceinline__ uint32_t pack_hi(float v0, float v1, float& r0, float& r1) {
    __nv_bfloat16 h0 = __float2bfloat16(v0), h1 = __float2bfloat16(v1);
    r0 = v0 - __bfloat162float(h0);
    r1 = v1 - __bfloat162float(h1);
    return ((uint32_t)__bfloat16_as_ushort(h1) << 16) | __bfloat16_as_ushort(h0);
}
__device__ __forceinline__ uint32_t pack_bf(float v0, float v1) {
    return ((uint32_t)__bfloat16_as_ushort(__float2bfloat16(v1)) << 16) |
           __bfloat16_as_ushort(__float2bfloat16(v0));
}
// unpack packed bf16x2 -> (lo, hi) floats
__device__ __forceinline__ void unpack_bf2(uint32_t p, float& lo, float& hi) {
    lo = __uint_as_float(p << 16);
    hi = __uint_as_float(p & 0xffff0000u);
}

// ==================== launch 0: fused init (detect + zero deg + weight convert) ==
__global__ void init_kernel(const int* __restrict__ ei32, int n_words,
                            const float* __restrict__ W1l, const float* __restrict__ W1r,
                            const float* __restrict__ W2l, const float* __restrict__ W2r) {
    int idx = blockIdx.x * blockDim.x + threadIdx.x;
    // dtype detection: warp 0 of block 0
    if (blockIdx.x == 0 && threadIdx.x < 32) {
        int lane = threadIdx.x;
        int wi = 1 + 2 * lane;
        int z = (wi < n_words && ei32[wi] == 0) ? 1 : 0;
        unsigned m = __ballot_sync(0xffffffffu, z);
        if (lane == 0) g_is64 = (__popc(m) > 24) ? 1 : 0;
    }
    if (idx < N_NODES) g_deg[idx] = 0;
    if (idx < 128 * 128) {                       // layer 1 weights: Ktot=128, Kh=64
        int n = idx >> 7, k = idx & 127;
        float v = (k < 64) ? W1l[n * 64 + k] : W1r[n * 64 + (k - 64)];
        __nv_bfloat16 h = __float2bfloat16(v);
        g_w1h[idx] = h;
        g_w1l[idx] = __float2bfloat16(v - __bfloat162float(h));
    } else if (idx < 128 * 128 + 128 * 256) {    // layer 2 weights: Ktot=256, Kh=128
        int j = idx - 128 * 128;
        int n = j >> 8, k = j & 255;
        float v = (k < 128) ? W2l[n * 128 + k] : W2r[n * 128 + (k - 128)];
        __nv_bfloat16 h = __float2bfloat16(v);
        g_w2h[j] = h;
        g_w2l[j] = __float2bfloat16(v - __bfloat162float(h));
    }
}

// ==================== CSR build ====================
__device__ __forceinline__ int load_idx(const void* ei, size_t pos) {
    if (g_is64) return (int)((const long long*)ei)[pos];
    return ((const int*)ei)[pos];
}
__global__ void hist_kernel(const void* __restrict__ ei, int E) {
    int e = blockIdx.x * blockDim.x + threadIdx.x;
    if (e < E) {
        int d = load_idx(ei, (size_t)E + e);
        g_dst32[e] = d;
        if ((unsigned)d < (unsigned)N_NODES) atomicAdd(&g_deg[d], 1);
    }
}
__global__ void scan_part_kernel() {
    __shared__ int s_woff[32];
    int tid = threadIdx.x, lane = tid & 31, wid = tid >> 5;
    int i = blockIdx.x * 1024 + tid;
    int v = (i < N_NODES) ? g_deg[i] : 0;
    int inc = v;
#pragma unroll
    for (int o = 1; o < 32; o <<= 1) {
        int t = __shfl_up_sync(0xffffffffu, inc, o);
        if (lane >= o) inc += t;
    }
    if (lane == 31) s_woff[wid] = inc;
    __syncthreads();
    if (wid == 0) {
        int ws = s_woff[lane];
        int wi = ws;
#pragma unroll
        for (int o = 1; o < 32; o <<= 1) {
            int t = __shfl_up_sync(0xffffffffu, wi, o);
            if (lane >= o) wi += t;
        }
        s_woff[lane] = wi - ws;
    }
    __syncthreads();
    int excl = s_woff[wid] + inc - v;
    if (i < N_NODES) g_offs[i] = excl;
    if (tid == 1023) g_part[blockIdx.x] = excl + v;
}
// each block computes its own prefix over the 98 partials (no extra kernel)
__global__ void scan_add_kernel() {
    __shared__ int redA[32], redB[32];
    __shared__ int s_off, s_tot;
    int tid = threadIdx.x, lane = tid & 31, wid = tid >> 5;
    int p  = (tid < NPART) ? g_part[tid] : 0;
    int v1 = (tid < (int)blockIdx.x) ? p : 0;   // exclusive prefix for this block
    int v2 = p;                                  // total
#pragma unroll
    for (int o = 16; o > 0; o >>= 1) {
        v1 += __shfl_xor_sync(0xffffffffu, v1, o);
        v2 += __shfl_xor_sync(0xffffffffu, v2, o);
    }
    if (lane == 0) { redA[wid] = v1; redB[wid] = v2; }
    __syncthreads();
    if (wid == 0) {
        int a = redA[lane], b = redB[lane];
#pragma unroll
        for (int o = 16; o > 0; o >>= 1) {
            a += __shfl_xor_sync(0xffffffffu, a, o);
            b += __shfl_xor_sync(0xffffffffu, b, o);
        }
        if (lane == 0) { s_off = a; s_tot = b; }
    }
    __syncthreads();
    int i = blockIdx.x * 1024 + tid;
    if (i < N_NODES) {
        int o = g_offs[i] + s_off;
        g_offs[i] = o;
        g_cursor[i] = o;
    }
    if (blockIdx.x == NPART - 1 && tid == 0) g_offs[N_NODES] = s_tot;
}
__global__ void scatter_kernel(const void* __restrict__ ei, int E) {
    int e = blockIdx.x * blockDim.x + threadIdx.x;
    if (e < E) {
        int d = g_dst32[e];
        int s = load_idx(ei, (size_t)e);
        if ((unsigned)d < (unsigned)N_NODES && (unsigned)s < (unsigned)N_NODES) {
            int p = atomicAdd(&g_cursor[d], 1);
            g_src_sorted[p] = s;
        }
    }
}

// ==================== fused aggregation + bf16 split ====================
// layer 1: mean(x nbrs) -> A1 cols 0..63 ; x row -> cols 64..127.
// Half-warp scheme: 2 edges per iteration, 16 lanes x float4 per edge.
__global__ void agg1_kernel(const float* __restrict__ x) {
    int w = (blockIdx.x * blockDim.x + threadIdx.x) >> 5;
    if (w >= N_NODES) return;
    int lane = threadIdx.x & 31;
    int half = lane >> 4, hl = lane & 15;
    int beg = g_offs[w], end = g_offs[w + 1];
    float inv = 1.0f / (float)max(end - beg, 1);
    float ax = 0.f, ay = 0.f, az = 0.f, aw = 0.f;
    for (int eb = beg; eb < end; eb += 32) {
        int n = min(32, end - eb);
        int s = (lane < n) ? g_src_sorted[eb + lane] : 0;
        int np = n >> 1;
        for (int t = 0; t < np; t++) {
            int ss = __shfl_sync(0xffffffffu, s, 2 * t + half);
            float4 v = *(const float4*)&x[(size_t)ss * 64 + hl * 4];
            ax += v.x; ay += v.y; az += v.z; aw += v.w;
        }
        if (n & 1) {
            int ss = __shfl_sync(0xffffffffu, s, n - 1);
            if (half == 0) {
                float4 v = *(const float4*)&x[(size_t)ss * 64 + hl * 4];
                ax += v.x; ay += v.y; az += v.z; aw += v.w;
            }
        }
    }
    ax += __shfl_xor_sync(0xffffffffu, ax, 16);
    ay += __shfl_xor_sync(0xffffffffu, ay, 16);
    az += __shfl_xor_sync(0xffffffffu, az, 16);
    aw += __shfl_xor_sync(0xffffffffu, aw, 16);
    if (half == 0) {
        ax *= inv; ay *= inv; az *= inv; aw *= inv;
        float r0, r1, r2, r3;
        uint32_t h0 = pack_hi(ax, ay, r0, r1);
        uint32_t h1 = pack_hi(az, aw, r2, r3);
        size_t base = (size_t)w * 128 + hl * 4;
        uint2 hv; hv.x = h0; hv.y = h1;
        uint2 lv; lv.x = pack_bf(r0, r1); lv.y = pack_bf(r2, r3);
        *(uint2*)&g_a1h[base] = hv;
        *(uint2*)&g_a1l[base] = lv;
    }
    // self part (cols 64..127), all 32 lanes
    float2 xv = *(const float2*)&x[(size_t)w * 64 + lane * 2];
    float r0, r1;
    uint32_t hp = pack_hi(xv.x, xv.y, r0, r1);
    size_t sb = (size_t)w * 128 + 64 + lane * 2;
    *(uint32_t*)&g_a1h[sb] = hp;
    *(uint32_t*)&g_a1l[sb] = pack_bf(r0, r1);
}
// layer 2: mean(h nbrs) -> A2 cols 0..127. h reconstructed as hi+lo from the
// A2 X-part (cols 128..255) that gemm1's epilogue wrote (error ~2^-17).
__global__ void agg2_kernel() {
    int w = (blockIdx.x * blockDim.x + threadIdx.x) >> 5;
    if (w >= N_NODES) return;
    int lane = threadIdx.x & 31;
    int beg = g_offs[w], end = g_offs[w + 1];
    float inv = 1.0f / (float)max(end - beg, 1);
    float ax = 0.f, ay = 0.f, az = 0.f, aw = 0.f;
    for (int eb = beg; eb < end; eb += 32) {
        int n = min(32, end - eb);
        int s = (lane < n) ? g_src_sorted[eb + lane] : 0;
        for (int t = 0; t < n; t++) {
            int ss = __shfl_sync(0xffffffffu, s, t);
            size_t base = (size_t)ss * 256 + 128 + lane * 4;
            uint2 ph = *(const uint2*)&g_a2h[base];
            uint2 pl = *(const uint2*)&g_a2l[base];
            float h0l, h0h, h1l, h1h, l0l, l0h, l1l, l1h;
            unpack_bf2(ph.x, h0l, h0h);
            unpack_bf2(ph.y, h1l, h1h);
            unpack_bf2(pl.x, l0l, l0h);
            unpack_bf2(pl.y, l1l, l1h);
            ax += h0l + l0l; ay += h0h + l0h;
            az += h1l + l1l; aw += h1h + l1h;
        }
    }
    ax *= inv; ay *= inv; az *= inv; aw *= inv;
    float r0, r1, r2, r3;
    uint32_t h0 = pack_hi(ax, ay, r0, r1);
    uint32_t h1 = pack_hi(az, aw, r2, r3);
    size_t base = (size_t)w * 256 + lane * 4;
    uint2 hv; hv.x = h0; hv.y = h1;
    uint2 lv; lv.x = pack_bf(r0, r1); lv.y = pack_bf(r2, r3);
    *(uint2*)&g_a2h[base] = hv;
    *(uint2*)&g_a2l[base] = lv;
}

// ==================== cp.async pipelined mma.sync GEMM ====================
// CTA 128x128, BK=16, 2-stage double buffer, RS=24 (48B rows: aligned + conflict-free).
// 8 warps, warp tile m32 x n64. 3-term split: AhBh + AhBl + AlBh.
template <int KT, bool RELU, int LAYER>
__global__ __launch_bounds__(256) void gemm_mma_kernel(
    const float* __restrict__ bias, float* __restrict__ out_ext)
{
    constexpr int NCH = KT / 16;
    constexpr int RS = 24;
    constexpr uint32_t ARR_B = 128 * RS * 2;
    constexpr uint32_t STG_B = 4 * ARR_B;
    __shared__ __align__(16) __nv_bfloat16 sbuf[2][4][128 * RS];   // 48 KB

    const __nv_bfloat16* Ah = (LAYER == 1) ? g_a1h : g_a2h;
    const __nv_bfloat16* Al = (LAYER == 1) ? g_a1l : g_a2l;
    const __nv_bfloat16* Wh = (LAYER == 1) ? g_w1h : g_w2h;
    const __nv_bfloat16* Wl = (LAYER == 1) ? g_w1l : g_w2l;

    const int tid = threadIdx.x, lane = tid & 31, wid = tid >> 5;
    const int row0 = blockIdx.x * 128;
    const int valid = min(128, N_NODES - row0);
    const int wr = wid & 3, wc = wid >> 2;

    float c[2][8][4];
#pragma unroll
    for (int mi = 0; mi < 2; mi++)
#pragma unroll
        for (int ni = 0; ni < 8; ni++)
#pragma unroll
            for (int q = 0; q < 4; q++) c[mi][ni][q] = 0.f;

    const uint32_t sb0 = smem_u32(sbuf);

    const int ld_r = tid >> 1, ld_u = tid & 1;
    const int ar = min(row0 + ld_r, N_NODES - 1);
    const size_t goA = (size_t)ar * KT + ld_u * 8;
    const size_t goW = (size_t)ld_r * KT + ld_u * 8;
    const uint32_t dst_ru = (uint32_t)(ld_r * RS + ld_u * 8) * 2;

    const int a_m = ((lane >> 3) & 1) * 8 + (lane & 7);
    const int a_u = (lane >> 4);
    const int b_n = ((lane >> 4) << 3) + (lane & 7);
    const int b_u = ((lane >> 3) & 1);

    {
        uint32_t d = sb0 + dst_ru;
        cp16(d + 0 * ARR_B, &Ah[goA]);
        cp16(d + 1 * ARR_B, &Al[goA]);
        cp16(d + 2 * ARR_B, &Wh[goW]);
        cp16(d + 3 * ARR_B, &Wl[goW]);
        CP_COMMIT();
    }

    for (int kc = 0; kc < NCH; kc++) {
        if (kc + 1 < NCH) {
            uint32_t d = sb0 + ((kc + 1) & 1) * STG_B + dst_ru;
            size_t ko = (size_t)(kc + 1) * 16;
            cp16(d + 0 * ARR_B, &Ah[goA + ko]);
            cp16(d + 1 * ARR_B, &Al[goA + ko]);
            cp16(d + 2 * ARR_B, &Wh[goW + ko]);
            cp16(d + 3 * ARR_B, &Wl[goW + ko]);
            CP_COMMIT();
            CP_WAIT1();
        } else {
            CP_WAIT0();
        }
        __syncthreads();

        const uint32_t sa  = sb0 + (kc & 1) * STG_B;
        const uint32_t sal = sa + 1 * ARR_B;
        const uint32_t sbh = sa + 2 * ARR_B;
        const uint32_t sbl = sa + 3 * ARR_B;

        uint32_t ah[2][4], alr[2][4], bh[8][2], bl[8][2];
#pragma unroll
        for (int mi = 0; mi < 2; mi++) {
            int rr = wr * 32 + mi * 16 + a_m;
            uint32_t off = (uint32_t)(rr * RS + a_u * 8) * 2;
            LDSM_X4(ah[mi][0], ah[mi][1], ah[mi][2], ah[mi][3], sa + off);
            LDSM_X4(alr[mi][0], alr[mi][1], alr[mi][2], alr[mi][3], sal + off);
        }
#pragma unroll
        for (int nj = 0; nj < 4; nj++) {
            int nr = wc * 64 + nj * 16 + b_n;
            uint32_t off = (uint32_t)(nr * RS + b_u * 8) * 2;
            LDSM_X4(bh[nj * 2][0], bh[nj * 2][1], bh[nj * 2 + 1][0], bh[nj * 2 + 1][1], sbh + off);
            LDSM_X4(bl[nj * 2][0], bl[nj * 2][1], bl[nj * 2 + 1][0], bl[nj * 2 + 1][1], sbl + off);
        }
#pragma unroll
        for (int mi = 0; mi < 2; mi++)
#pragma unroll
            for (int ni = 0; ni < 8; ni++) {
                MMA16816(c[mi][ni], ah[mi], bh[ni]);
                MMA16816(c[mi][ni], ah[mi], bl[ni]);
                MMA16816(c[mi][ni], alr[mi], bh[ni]);
            }
        __syncthreads();
    }

    // ---- epilogue ----
    const int g = lane >> 2, tg = lane & 3;
#pragma unroll
    for (int ni = 0; ni < 8; ni++) {
        int col = wc * 64 + ni * 8 + tg * 2;
        float2 bv = *(const float2*)&bias[col];
#pragma unroll
        for (int mi = 0; mi < 2; mi++) {
            int rl = wr * 32 + mi * 16 + g;
#pragma unroll
            for (int hrow = 0; hrow < 2; hrow++) {
                int r = rl + hrow * 8;
                if (r >= valid) continue;
                float v0 = c[mi][ni][hrow * 2 + 0] + bv.x;
                float v1 = c[mi][ni][hrow * 2 + 1] + bv.y;
                if (RELU) { v0 = fmaxf(v0, 0.f); v1 = fmaxf(v1, 0.f); }
                size_t grow = (size_t)(row0 + r);
                if (LAYER == 1) {
                    float r0, r1;
                    uint32_t hp = pack_hi(v0, v1, r0, r1);   // h as bf16 hi/lo (A2 X-part)
                    *(uint32_t*)&g_a2h[grow * 256 + 128 + col] = hp;
                    *(uint32_t*)&g_a2l[grow * 256 + 128 + col] = pack_bf(r0, r1);
                } else {
                    float2 o; o.x = v0; o.y = v1;
                    *(float2*)&out_ext[grow * 128 + col] = o;
                }
            }
        }
    }
}

// ==================== entry point ====================
extern "C" void kernel_launch(void* const* d_in, const int* in_sizes, int n_in,
                              void* d_out, int out_size)
{
    (void)n_in; (void)out_size;
    const float* x   = (const float*)d_in[0];
    const void*  ei  = d_in[1];
    const float* W1l = (const float*)d_in[2];
    const float* W1r = (const float*)d_in[3];
    const float* b1  = (const float*)d_in[4];
    const float* W2l = (const float*)d_in[5];
    const float* W2r = (const float*)d_in[6];
    const float* b2  = (const float*)d_in[7];
    float*       out = (float*)d_out;

    int E = in_sizes[1] / 2;
    if (E > E_MAX) E = E_MAX;

    const int agg_blocks  = (N_NODES * 32 + 255) / 256;   // warp per node
    const int gemm_blocks = (N_NODES + 127) / 128;        // 782

    // launch order fixed so that index 5 (ncu -s 5 -c 1) is agg1_kernel
    init_kernel<<<(N_NODES + 255) / 256, 256>>>((const int*)ei, in_sizes[1],
                                                W1l, W1r, W2l, W2r);      // 0
    hist_kernel<<<(E + 255) / 256, 256>>>(ei, E);                          // 1
    scan_part_kernel<<<NPART, 1024>>>();                                   // 2
    scan_add_kernel<<<NPART, 1024>>>();                                    // 3
    scatter_kernel<<<(E + 255) / 256, 256>>>(ei, E);                       // 4
    agg1_kernel<<<agg_blocks, 256>>>(x);                                   // 5 <- profiled
    gemm_mma_kernel<128, true, 1><<<gemm_blocks, 256>>>(b1, nullptr);      // 6
    agg2_kernel<<<agg_blocks, 256>>>();                                    // 7
    gemm_mma_kernel<256, false, 2><<<gemm_blocks, 256>>>(b2, out);         // 8
}

// round 7
// speedup vs baseline: 1.1491x; 1.1491x over previous
#include <cuda_runtime.h>
#include <cuda_bf16.h>
#include <cstdint>

#define N_NODES 100000
#define E_MAX   1600000
#define NPART   98          // ceil(100000/1024)

// ---------------- device scratch (static; no dynamic allocation) ----------------
__device__ int   g_is64;
__device__ int   g_deg[N_NODES];
__device__ int   g_offs[N_NODES + 1];
__device__ int   g_cursor[N_NODES];
__device__ int   g_part[NPART];
__device__ int   g_dst32[E_MAX];
__device__ int   g_src_sorted[E_MAX];
// fp32 (tf32-rounded) operands:  A1 = [agg1 | x]  (stride 128),  A2 = [agg2 | h] (stride 256)
__device__ float g_A1[(size_t)N_NODES * 128];
__device__ float g_A2[(size_t)N_NODES * 256];
__device__ float g_w1[128 * 128];    // [n][k] concat(W1l, W1r)
__device__ float g_w2[128 * 256];    // [n][k] concat(W2l, W2r)

// ==================== PTX helpers (family-portable) ====================
__device__ __forceinline__ uint32_t smem_u32(const void* p) {
    uint32_t a;
    asm("{ .reg .u64 t; cvta.to.shared.u64 t, %1; cvt.u32.u64 %0, t; }" : "=r"(a) : "l"(p));
    return a;
}
__device__ __forceinline__ float tf32r(float v) {
    float o;
    asm("cvt.rna.tf32.f32 %0, %1;" : "=f"(o) : "f"(v));
    return o;
}
#define MMA1688(c, a, b)                                                         \
    asm volatile("mma.sync.aligned.m16n8k8.row.col.f32.tf32.tf32.f32 "           \
                 "{%0,%1,%2,%3}, {%4,%5,%6,%7}, {%8,%9}, {%0,%1,%2,%3};"         \
                 : "+f"((c)[0]), "+f"((c)[1]), "+f"((c)[2]), "+f"((c)[3])        \
                 : "r"((a)[0]), "r"((a)[1]), "r"((a)[2]), "r"((a)[3]),           \
                   "r"((b)[0]), "r"((b)[1]))
__device__ __forceinline__ void cp16(uint32_t dst, const void* src) {
    asm volatile("cp.async.cg.shared.global [%0], [%1], 16;" :: "r"(dst), "l"(src));
}
#define CP_COMMIT() asm volatile("cp.async.commit_group;" ::: "memory")
#define CP_WAIT1()  asm volatile("cp.async.wait_group 1;" ::: "memory")
#define CP_WAIT0()  asm volatile("cp.async.wait_group 0;" ::: "memory")

// ==================== launch 0: fused init (detect + zero deg + weight concat) ==
__global__ void init_kernel(const int* __restrict__ ei32, int n_words,
                            const float* __restrict__ W1l, const float* __restrict__ W1r,
                            const float* __restrict__ W2l, const float* __restrict__ W2r) {
    int idx = blockIdx.x * blockDim.x + threadIdx.x;
    if (blockIdx.x == 0 && threadIdx.x < 32) {
        int lane = threadIdx.x;
        int wi = 1 + 2 * lane;
        int z = (wi < n_words && ei32[wi] == 0) ? 1 : 0;
        unsigned m = __ballot_sync(0xffffffffu, z);
        if (lane == 0) g_is64 = (__popc(m) > 24) ? 1 : 0;
    }
    if (idx < N_NODES) g_deg[idx] = 0;
    if (idx < 128 * 128) {                       // layer 1: Ktot=128, Kh=64
        int n = idx >> 7, k = idx & 127;
        float v = (k < 64) ? W1l[n * 64 + k] : W1r[n * 64 + (k - 64)];
        g_w1[idx] = tf32r(v);
    } else if (idx < 128 * 128 + 128 * 256) {    // layer 2: Ktot=256, Kh=128
        int j = idx - 128 * 128;
        int n = j >> 8, k = j & 255;
        float v = (k < 128) ? W2l[n * 128 + k] : W2r[n * 128 + (k - 128)];
        g_w2[j] = tf32r(v);
    }
}

// ==================== CSR build ====================
__device__ __forceinline__ int load_idx(const void* ei, size_t pos) {
    if (g_is64) return (int)((const long long*)ei)[pos];
    return ((const int*)ei)[pos];
}
__global__ void hist_kernel(const void* __restrict__ ei, int E) {
    int e = blockIdx.x * blockDim.x + threadIdx.x;
    if (e < E) {
        int d = load_idx(ei, (size_t)E + e);
        g_dst32[e] = d;
        if ((unsigned)d < (unsigned)N_NODES) atomicAdd(&g_deg[d], 1);
    }
}
__global__ void scan_part_kernel() {
    __shared__ int s_woff[32];
    int tid = threadIdx.x, lane = tid & 31, wid = tid >> 5;
    int i = blockIdx.x * 1024 + tid;
    int v = (i < N_NODES) ? g_deg[i] : 0;
    int inc = v;
#pragma unroll
    for (int o = 1; o < 32; o <<= 1) {
        int t = __shfl_up_sync(0xffffffffu, inc, o);
        if (lane >= o) inc += t;
    }
    if (lane == 31) s_woff[wid] = inc;
    __syncthreads();
    if (wid == 0) {
        int ws = s_woff[lane];
        int wi = ws;
#pragma unroll
        for (int o = 1; o < 32; o <<= 1) {
            int t = __shfl_up_sync(0xffffffffu, wi, o);
            if (lane >= o) wi += t;
        }
        s_woff[lane] = wi - ws;
    }
    __syncthreads();
    int excl = s_woff[wid] + inc - v;
    if (i < N_NODES) g_offs[i] = excl;
    if (tid == 1023) g_part[blockIdx.x] = excl + v;
}
__global__ void scan_add_kernel() {     // each block self-computes its prefix over 98 partials
    __shared__ int redA[32], redB[32];
    __shared__ int s_off, s_tot;
    int tid = threadIdx.x, lane = tid & 31, wid = tid >> 5;
    int p  = (tid < NPART) ? g_part[tid] : 0;
    int v1 = (tid < (int)blockIdx.x) ? p : 0;
    int v2 = p;
#pragma unroll
    for (int o = 16; o > 0; o >>= 1) {
        v1 += __shfl_xor_sync(0xffffffffu, v1, o);
        v2 += __shfl_xor_sync(0xffffffffu, v2, o);
    }
    if (lane == 0) { redA[wid] = v1; redB[wid] = v2; }
    __syncthreads();
    if (wid == 0) {
        int a = redA[lane], b = redB[lane];
#pragma unroll
        for (int o = 16; o > 0; o >>= 1) {
            a += __shfl_xor_sync(0xffffffffu, a, o);
            b += __shfl_xor_sync(0xffffffffu, b, o);
        }
        if (lane == 0) { s_off = a; s_tot = b; }
    }
    __syncthreads();
    int i = blockIdx.x * 1024 + tid;
    if (i < N_NODES) {
        int o = g_offs[i] + s_off;
        g_offs[i] = o;
        g_cursor[i] = o;
    }
    if (blockIdx.x == NPART - 1 && tid == 0) g_offs[N_NODES] = s_tot;
}
__global__ void scatter_kernel(const void* __restrict__ ei, int E) {
    int e = blockIdx.x * blockDim.x + threadIdx.x;
    if (e < E) {
        int d = g_dst32[e];
        int s = load_idx(ei, (size_t)e);
        if ((unsigned)d < (unsigned)N_NODES && (unsigned)s < (unsigned)N_NODES) {
            int p = atomicAdd(&g_cursor[d], 1);
            g_src_sorted[p] = s;
        }
    }
}

// ==================== fused aggregation (warp per node, fp32/tf32) ====================
// layer 1: A1 = [ mean(x nbrs) | x ], tf32-rounded
__global__ void agg1_kernel(const float* __restrict__ x) {
    int w = (blockIdx.x * blockDim.x + threadIdx.x) >> 5;
    if (w >= N_NODES) return;
    int lane = threadIdx.x & 31;
    int beg = g_offs[w], end = g_offs[w + 1];
    float inv = 1.0f / (float)max(end - beg, 1);
    float ax = 0.f, ay = 0.f;
    for (int eb = beg; eb < end; eb += 32) {
        int n = min(32, end - eb);
        int s = (lane < n) ? g_src_sorted[eb + lane] : 0;
        for (int t = 0; t < n; t++) {
            int ss = __shfl_sync(0xffffffffu, s, t);
            float2 v = *(const float2*)&x[(size_t)ss * 64 + lane * 2];
            ax += v.x; ay += v.y;
        }
    }
    float2 o; o.x = tf32r(ax * inv); o.y = tf32r(ay * inv);
    *(float2*)&g_A1[(size_t)w * 128 + lane * 2] = o;
    float2 xv = *(const float2*)&x[(size_t)w * 64 + lane * 2];
    float2 xo; xo.x = tf32r(xv.x); xo.y = tf32r(xv.y);
    *(float2*)&g_A1[(size_t)w * 128 + 64 + lane * 2] = xo;
}
// layer 2: A2 cols 0..127 = mean of h (h = A2 cols 128..255, written by gemm1 epilogue)
__global__ void agg2_kernel() {
    int w = (blockIdx.x * blockDim.x + threadIdx.x) >> 5;
    if (w >= N_NODES) return;
    int lane = threadIdx.x & 31;
    int beg = g_offs[w], end = g_offs[w + 1];
    float inv = 1.0f / (float)max(end - beg, 1);
    float ax = 0.f, ay = 0.f, az = 0.f, aw = 0.f;
    for (int eb = beg; eb < end; eb += 32) {
        int n = min(32, end - eb);
        int s = (lane < n) ? g_src_sorted[eb + lane] : 0;
        for (int t = 0; t < n; t++) {
            int ss = __shfl_sync(0xffffffffu, s, t);
            float4 v = *(const float4*)&g_A2[(size_t)ss * 256 + 128 + lane * 4];
            ax += v.x; ay += v.y; az += v.z; aw += v.w;
        }
    }
    float4 o;
    o.x = tf32r(ax * inv); o.y = tf32r(ay * inv);
    o.z = tf32r(az * inv); o.w = tf32r(aw * inv);
    *(float4*)&g_A2[(size_t)w * 256 + lane * 4] = o;
}

// ==================== cp.async pipelined tf32 mma GEMM ====================
// CTA 128x128, BK=16 fp32, 2-stage double buffer, RS=20 floats/row (80B:
// 16B-aligned for cp.async; fragment LDS.32 conflict-free since 20r+k hits 32
// distinct banks over g=0..7, k=0..3). 8 warps, warp tile m32 x n64.
template <int KT, bool RELU, int LAYER>
__global__ __launch_bounds__(256) void gemm_tf32_kernel(
    const float* __restrict__ bias, float* __restrict__ out_ext)
{
    constexpr int NCH = KT / 16;
    constexpr int RS = 20;                        // floats per smem row
    constexpr uint32_t ARR_B = 128 * RS * 4;      // 10240 B per array
    constexpr uint32_t STG_B = 2 * ARR_B;         // A + B per stage
    __shared__ __align__(16) float sbuf[2][2][128 * RS];   // 40 KB

    const float* A = (LAYER == 1) ? g_A1 : g_A2;
    const float* W = (LAYER == 1) ? g_w1 : g_w2;

    const int tid = threadIdx.x, lane = tid & 31, wid = tid >> 5;
    const int row0 = blockIdx.x * 128;
    const int valid = min(128, N_NODES - row0);
    const int wr = wid & 3, wc = wid >> 2;

    float c[2][8][4];
#pragma unroll
    for (int mi = 0; mi < 2; mi++)
#pragma unroll
        for (int ni = 0; ni < 8; ni++)
#pragma unroll
            for (int q = 0; q < 4; q++) c[mi][ni][q] = 0.f;

    const uint32_t sb0 = smem_u32(sbuf);

    // cp.async mapping: 128 rows x 4x16B units per array; thread does 2 units of A + 2 of B
    const int ld_r = tid >> 1;
    const int ld_u = (tid & 1) * 2;
    const int ar = min(row0 + ld_r, N_NODES - 1);
    const size_t goA = (size_t)ar * KT + ld_u * 4;
    const size_t goW = (size_t)ld_r * KT + ld_u * 4;
    const uint32_t dst_ru = (uint32_t)(ld_r * RS + ld_u * 4) * 4;

    const int g  = lane >> 2;       // fragment group row
    const int t4 = lane & 3;        // fragment k index

    {
        uint32_t d = sb0 + dst_ru;
        cp16(d, &A[goA]);            cp16(d + 16, &A[goA + 4]);
        cp16(d + ARR_B, &W[goW]);    cp16(d + ARR_B + 16, &W[goW + 4]);
        CP_COMMIT();
    }

    for (int kc = 0; kc < NCH; kc++) {
        if (kc + 1 < NCH) {
            uint32_t d = sb0 + ((kc + 1) & 1) * STG_B + dst_ru;
            size_t ko = (size_t)(kc + 1) * 16;
            cp16(d, &A[goA + ko]);            cp16(d + 16, &A[goA + ko + 4]);
            cp16(d + ARR_B, &W[goW + ko]);    cp16(d + ARR_B + 16, &W[goW + ko + 4]);
            CP_COMMIT();
            CP_WAIT1();
        } else {
            CP_WAIT0();
        }
        __syncthreads();

        const float* sa = &sbuf[kc & 1][0][0];
        const float* sw = &sbuf[kc & 1][1][0];

#pragma unroll
        for (int ks = 0; ks < 2; ks++) {
            uint32_t af[2][4], bf[8][2];
#pragma unroll
            for (int mi = 0; mi < 2; mi++) {
                int r = wr * 32 + mi * 16 + g;
                int k = ks * 8 + t4;
                af[mi][0] = __float_as_uint(sa[r * RS + k]);
                af[mi][1] = __float_as_uint(sa[(r + 8) * RS + k]);
                af[mi][2] = __float_as_uint(sa[r * RS + k + 4]);
                af[mi][3] = __float_as_uint(sa[(r + 8) * RS + k + 4]);
            }
#pragma unroll
            for (int ni = 0; ni < 8; ni++) {
                int n = wc * 64 + ni * 8 + g;
                int k = ks * 8 + t4;
                bf[ni][0] = __float_as_uint(sw[n * RS + k]);
                bf[ni][1] = __float_as_uint(sw[n * RS + k + 4]);
            }
#pragma unroll
            for (int mi = 0; mi < 2; mi++)
#pragma unroll
                for (int ni = 0; ni < 8; ni++)
                    MMA1688(c[mi][ni], af[mi], bf[ni]);
        }
        __syncthreads();
    }

    // ---- epilogue: bias + (relu); layer1 -> h into A2 cols 128..255 (tf32) ----
    const int tg = lane & 3;
#pragma unroll
    for (int ni = 0; ni < 8; ni++) {
        int col = wc * 64 + ni * 8 + tg * 2;
        float2 bv = *(const float2*)&bias[col];
#pragma unroll
        for (int mi = 0; mi < 2; mi++) {
            int rl = wr * 32 + mi * 16 + g;
#pragma unroll
            for (int hrow = 0; hrow < 2; hrow++) {
                int r = rl + hrow * 8;
                if (r >= valid) continue;
                float v0 = c[mi][ni][hrow * 2 + 0] + bv.x;
                float v1 = c[mi][ni][hrow * 2 + 1] + bv.y;
                if (RELU) { v0 = fmaxf(v0, 0.f); v1 = fmaxf(v1, 0.f); }
                size_t grow = (size_t)(row0 + r);
                if (LAYER == 1) {
                    float2 o; o.x = tf32r(v0); o.y = tf32r(v1);
                    *(float2*)&g_A2[grow * 256 + 128 + col] = o;
                } else {
                    float2 o; o.x = v0; o.y = v1;
                    *(float2*)&out_ext[grow * 128 + col] = o;
                }
            }
        }
    }
}

// ==================== entry point ====================
extern "C" void kernel_launch(void* const* d_in, const int* in_sizes, int n_in,
                              void* d_out, int out_size)
{
    (void)n_in; (void)out_size;
    const float* x   = (const float*)d_in[0];
    const void*  ei  = d_in[1];
    const float* W1l = (const float*)d_in[2];
    const float* W1r = (const float*)d_in[3];
    const float* b1  = (const float*)d_in[4];
    const float* W2l = (const float*)d_in[5];
    const float* W2r = (const float*)d_in[6];
    const float* b2  = (const float*)d_in[7];
    float*       out = (float*)d_out;

    int E = in_sizes[1] / 2;
    if (E > E_MAX) E = E_MAX;

    const int agg_blocks  = (N_NODES * 32 + 255) / 256;   // warp per node
    const int gemm_blocks = (N_NODES + 127) / 128;        // 782

    init_kernel<<<(N_NODES + 255) / 256, 256>>>((const int*)ei, in_sizes[1],
                                                W1l, W1r, W2l, W2r);       // 0
    hist_kernel<<<(E + 255) / 256, 256>>>(ei, E);                           // 1
    scan_part_kernel<<<NPART, 1024>>>();                                    // 2
    scan_add_kernel<<<NPART, 1024>>>();                                     // 3
    scatter_kernel<<<(E + 255) / 256, 256>>>(ei, E);                        // 4
    agg1_kernel<<<agg_blocks, 256>>>(x);                                    // 5 <- profiled
    gemm_tf32_kernel<128, true, 1><<<gemm_blocks, 256>>>(b1, nullptr);      // 6
    agg2_kernel<<<agg_blocks, 256>>>();                                     // 7
    gemm_tf32_kernel<256, false, 2><<<gemm_blocks, 256>>>(b2, out);         // 8
}

// round 8
// speedup vs baseline: 1.5250x; 1.3272x over previous
#include <cuda_runtime.h>
#include <cuda_fp16.h>
#include <cstdint>

#define N_NODES 100000
#define E_MAX   1600000
#define NPART   98          // ceil(100000/1024)

// ---------------- device scratch (static; no dynamic allocation) ----------------
__device__ int    g_is64;
__device__ int    g_deg[N_NODES];
__device__ int    g_offs[N_NODES + 1];
__device__ int    g_cursor[N_NODES];
__device__ int    g_part[NPART];
__device__ int    g_dst32[E_MAX];
__device__ int    g_src_sorted[E_MAX];
// fp16 operands:  A1 = [agg1 | x] (stride 128),  A2 = [agg2 | h] (stride 256)
__device__ __half g_A1[(size_t)N_NODES * 128];
__device__ __half g_A2[(size_t)N_NODES * 256];
__device__ __half g_w1[128 * 128];    // [n][k] concat(W1l, W1r)
__device__ __half g_w2[128 * 256];    // [n][k] concat(W2l, W2r)

// ==================== PTX helpers (family-portable) ====================
__device__ __forceinline__ uint32_t smem_u32(const void* p) {
    uint32_t a;
    asm("{ .reg .u64 t; cvta.to.shared.u64 t, %1; cvt.u32.u64 %0, t; }" : "=r"(a) : "l"(p));
    return a;
}
#define LDSM_X4(r0, r1, r2, r3, addr)                                           \
    asm volatile("ldmatrix.sync.aligned.m8n8.x4.shared.b16 {%0,%1,%2,%3}, [%4];" \
                 : "=r"(r0), "=r"(r1), "=r"(r2), "=r"(r3) : "r"(addr))
#define MMA16816F(c, a, b)                                                       \
    asm volatile("mma.sync.aligned.m16n8k16.row.col.f32.f16.f16.f32 "            \
                 "{%0,%1,%2,%3}, {%4,%5,%6,%7}, {%8,%9}, {%0,%1,%2,%3};"         \
                 : "+f"((c)[0]), "+f"((c)[1]), "+f"((c)[2]), "+f"((c)[3])        \
                 : "r"((a)[0]), "r"((a)[1]), "r"((a)[2]), "r"((a)[3]),           \
                   "r"((b)[0]), "r"((b)[1]))
__device__ __forceinline__ void cp16(uint32_t dst, const void* src) {
    asm volatile("cp.async.cg.shared.global [%0], [%1], 16;" :: "r"(dst), "l"(src));
}
#define CP_COMMIT() asm volatile("cp.async.commit_group;" ::: "memory")
#define CP_WAIT1()  asm volatile("cp.async.wait_group 1;" ::: "memory")
#define CP_WAIT0()  asm volatile("cp.async.wait_group 0;" ::: "memory")

__device__ __forceinline__ uint32_t pack_h2(float a, float b) {
    __half2 h = __floats2half2_rn(a, b);
    return *(uint32_t*)&h;
}

// ==================== launch 0: fused init (detect + zero deg + weight concat) ==
__global__ void init_kernel(const int* __restrict__ ei32, int n_words,
                            const float* __restrict__ W1l, const float* __restrict__ W1r,
                            const float* __restrict__ W2l, const float* __restrict__ W2r) {
    int idx = blockIdx.x * blockDim.x + threadIdx.x;
    if (blockIdx.x == 0 && threadIdx.x < 32) {
        int lane = threadIdx.x;
        int wi = 1 + 2 * lane;
        int z = (wi < n_words && ei32[wi] == 0) ? 1 : 0;
        unsigned m = __ballot_sync(0xffffffffu, z);
        if (lane == 0) g_is64 = (__popc(m) > 24) ? 1 : 0;
    }
    if (idx < N_NODES) g_deg[idx] = 0;
    if (idx < 128 * 128) {                       // layer 1: Ktot=128, Kh=64
        int n = idx >> 7, k = idx & 127;
        float v = (k < 64) ? W1l[n * 64 + k] : W1r[n * 64 + (k - 64)];
        g_w1[idx] = __float2half_rn(v);
    } else if (idx < 128 * 128 + 128 * 256) {    // layer 2: Ktot=256, Kh=128
        int j = idx - 128 * 128;
        int n = j >> 8, k = j & 255;
        float v = (k < 128) ? W2l[n * 128 + k] : W2r[n * 128 + (k - 128)];
        g_w2[j] = __float2half_rn(v);
    }
}

// ==================== CSR build ====================
__device__ __forceinline__ int load_idx(const void* ei, size_t pos) {
    if (g_is64) return (int)((const long long*)ei)[pos];
    return ((const int*)ei)[pos];
}
__global__ void hist_kernel(const void* __restrict__ ei, int E) {
    int e = blockIdx.x * blockDim.x + threadIdx.x;
    if (e < E) {
        int d = load_idx(ei, (size_t)E + e);
        g_dst32[e] = d;
        if ((unsigned)d < (unsigned)N_NODES) atomicAdd(&g_deg[d], 1);
    }
}
__global__ void scan_part_kernel() {
    __shared__ int s_woff[32];
    int tid = threadIdx.x, lane = tid & 31, wid = tid >> 5;
    int i = blockIdx.x * 1024 + tid;
    int v = (i < N_NODES) ? g_deg[i] : 0;
    int inc = v;
#pragma unroll
    for (int o = 1; o < 32; o <<= 1) {
        int t = __shfl_up_sync(0xffffffffu, inc, o);
        if (lane >= o) inc += t;
    }
    if (lane == 31) s_woff[wid] = inc;
    __syncthreads();
    if (wid == 0) {
        int ws = s_woff[lane];
        int wi = ws;
#pragma unroll
        for (int o = 1; o < 32; o <<= 1) {
            int t = __shfl_up_sync(0xffffffffu, wi, o);
            if (lane >= o) wi += t;
        }
        s_woff[lane] = wi - ws;
    }
    __syncthreads();
    int excl = s_woff[wid] + inc - v;
    if (i < N_NODES) g_offs[i] = excl;
    if (tid == 1023) g_part[blockIdx.x] = excl + v;
}
__global__ void scan_add_kernel() {     // each block self-computes its prefix over 98 partials
    __shared__ int redA[32], redB[32];
    __shared__ int s_off, s_tot;
    int tid = threadIdx.x, lane = tid & 31, wid = tid >> 5;
    int p  = (tid < NPART) ? g_part[tid] : 0;
    int v1 = (tid < (int)blockIdx.x) ? p : 0;
    int v2 = p;
#pragma unroll
    for (int o = 16; o > 0; o >>= 1) {
        v1 += __shfl_xor_sync(0xffffffffu, v1, o);
        v2 += __shfl_xor_sync(0xffffffffu, v2, o);
    }
    if (lane == 0) { redA[wid] = v1; redB[wid] = v2; }
    __syncthreads();
    if (wid == 0) {
        int a = redA[lane], b = redB[lane];
#pragma unroll
        for (int o = 16; o > 0; o >>= 1) {
            a += __shfl_xor_sync(0xffffffffu, a, o);
            b += __shfl_xor_sync(0xffffffffu, b, o);
        }
        if (lane == 0) { s_off = a; s_tot = b; }
    }
    __syncthreads();
    int i = blockIdx.x * 1024 + tid;
    if (i < N_NODES) {
        int o = g_offs[i] + s_off;
        g_offs[i] = o;
        g_cursor[i] = o;
    }
    if (blockIdx.x == NPART - 1 && tid == 0) g_offs[N_NODES] = s_tot;
}
__global__ void scatter_kernel(const void* __restrict__ ei, int E) {
    int e = blockIdx.x * blockDim.x + threadIdx.x;
    if (e < E) {
        int d = g_dst32[e];
        int s = load_idx(ei, (size_t)e);
        if ((unsigned)d < (unsigned)N_NODES && (unsigned)s < (unsigned)N_NODES) {
            int p = atomicAdd(&g_cursor[d], 1);
            g_src_sorted[p] = s;
        }
    }
}

// ==================== fused aggregation (warp per node) ====================
// layer 1: A1 = [ mean(x nbrs) | x ] as fp16 (x gathered in fp32)
__global__ void agg1_kernel(const float* __restrict__ x) {
    int w = (blockIdx.x * blockDim.x + threadIdx.x) >> 5;
    if (w >= N_NODES) return;
    int lane = threadIdx.x & 31;
    int beg = g_offs[w], end = g_offs[w + 1];
    float inv = 1.0f / (float)max(end - beg, 1);
    float ax = 0.f, ay = 0.f;
    for (int eb = beg; eb < end; eb += 32) {
        int n = min(32, end - eb);
        int s = (lane < n) ? g_src_sorted[eb + lane] : 0;
        for (int t = 0; t < n; t++) {
            int ss = __shfl_sync(0xffffffffu, s, t);
            float2 v = *(const float2*)&x[(size_t)ss * 64 + lane * 2];
            ax += v.x; ay += v.y;
        }
    }
    size_t base = (size_t)w * 128 + lane * 2;
    *(uint32_t*)&g_A1[base] = pack_h2(ax * inv, ay * inv);
    float2 xv = *(const float2*)&x[(size_t)w * 64 + lane * 2];
    *(uint32_t*)&g_A1[base + 64] = pack_h2(xv.x, xv.y);
}
// layer 2: A2 cols 0..127 = mean of h-fp16 (cols 128..255, written by gemm1 epilogue)
__global__ void agg2_kernel() {
    int w = (blockIdx.x * blockDim.x + threadIdx.x) >> 5;
    if (w >= N_NODES) return;
    int lane = threadIdx.x & 31;
    int beg = g_offs[w], end = g_offs[w + 1];
    float inv = 1.0f / (float)max(end - beg, 1);
    float ax = 0.f, ay = 0.f, az = 0.f, aw = 0.f;
    for (int eb = beg; eb < end; eb += 32) {
        int n = min(32, end - eb);
        int s = (lane < n) ? g_src_sorted[eb + lane] : 0;
        for (int t = 0; t < n; t++) {
            int ss = __shfl_sync(0xffffffffu, s, t);
            uint2 p = *(const uint2*)&g_A2[(size_t)ss * 256 + 128 + lane * 4];
            float2 f0 = __half22float2(*(__half2*)&p.x);
            float2 f1 = __half22float2(*(__half2*)&p.y);
            ax += f0.x; ay += f0.y; az += f1.x; aw += f1.y;
        }
    }
    uint2 o;
    o.x = pack_h2(ax * inv, ay * inv);
    o.y = pack_h2(az * inv, aw * inv);
    *(uint2*)&g_A2[(size_t)w * 256 + lane * 4] = o;
}

// ==================== cp.async pipelined fp16 mma GEMM ====================
// CTA 128x128, BK=16 halves, 2-stage double buffer, RS=24 halves (48B rows:
// aligned + ldmatrix conflict-free — layout identical to validated round-5 bf16).
// 8 warps, warp tile m32 x n64, single pass (16 MMAs per chunk-warp).
template <int KT, bool RELU, int LAYER>
__global__ __launch_bounds__(256) void gemm_fp16_kernel(
    const float* __restrict__ bias, float* __restrict__ out_ext)
{
    constexpr int NCH = KT / 16;
    constexpr int RS = 24;
    constexpr uint32_t ARR_B = 128 * RS * 2;      // 6144 B per array
    constexpr uint32_t STG_B = 2 * ARR_B;         // A + W per stage
    __shared__ __align__(16) __half sbuf[2][2][128 * RS];   // 24 KB

    const __half* A = (LAYER == 1) ? g_A1 : g_A2;
    const __half* W = (LAYER == 1) ? g_w1 : g_w2;

    const int tid = threadIdx.x, lane = tid & 31, wid = tid >> 5;
    const int row0 = blockIdx.x * 128;
    const int valid = min(128, N_NODES - row0);
    const int wr = wid & 3, wc = wid >> 2;

    float c[2][8][4];
#pragma unroll
    for (int mi = 0; mi < 2; mi++)
#pragma unroll
        for (int ni = 0; ni < 8; ni++)
#pragma unroll
            for (int q = 0; q < 4; q++) c[mi][ni][q] = 0.f;

    const uint32_t sb0 = smem_u32(sbuf);

    // cp.async mapping: 128 rows x 2 16B-units; each thread: 1 unit A + 1 unit W
    const int ld_r = tid >> 1, ld_u = tid & 1;
    const int ar = min(row0 + ld_r, N_NODES - 1);
    const size_t goA = (size_t)ar * KT + ld_u * 8;
    const size_t goW = (size_t)ld_r * KT + ld_u * 8;
    const uint32_t dst_ru = (uint32_t)(ld_r * RS + ld_u * 8) * 2;

    const int a_m = ((lane >> 3) & 1) * 8 + (lane & 7);
    const int a_u = (lane >> 4);
    const int b_n = ((lane >> 4) << 3) + (lane & 7);
    const int b_u = ((lane >> 3) & 1);

    {
        uint32_t d = sb0 + dst_ru;
        cp16(d, &A[goA]);
        cp16(d + ARR_B, &W[goW]);
        CP_COMMIT();
    }

    for (int kc = 0; kc < NCH; kc++) {
        if (kc + 1 < NCH) {
            uint32_t d = sb0 + ((kc + 1) & 1) * STG_B + dst_ru;
            size_t ko = (size_t)(kc + 1) * 16;
            cp16(d, &A[goA + ko]);
            cp16(d + ARR_B, &W[goW + ko]);
            CP_COMMIT();
            CP_WAIT1();
        } else {
            CP_WAIT0();
        }
        __syncthreads();

        const uint32_t sa = sb0 + (kc & 1) * STG_B;
        const uint32_t sw = sa + ARR_B;

        uint32_t af[2][4], bf[8][2];
#pragma unroll
        for (int mi = 0; mi < 2; mi++) {
            int rr = wr * 32 + mi * 16 + a_m;
            uint32_t off = (uint32_t)(rr * RS + a_u * 8) * 2;
            LDSM_X4(af[mi][0], af[mi][1], af[mi][2], af[mi][3], sa + off);
        }
#pragma unroll
        for (int nj = 0; nj < 4; nj++) {
            int nr = wc * 64 + nj * 16 + b_n;
            uint32_t off = (uint32_t)(nr * RS + b_u * 8) * 2;
            LDSM_X4(bf[nj * 2][0], bf[nj * 2][1], bf[nj * 2 + 1][0], bf[nj * 2 + 1][1], sw + off);
        }
#pragma unroll
        for (int mi = 0; mi < 2; mi++)
#pragma unroll
            for (int ni = 0; ni < 8; ni++)
                MMA16816F(c[mi][ni], af[mi], bf[ni]);
        __syncthreads();
    }

    // ---- epilogue: bias + (relu); layer1 -> h (fp16) into A2 cols 128..255 ----
    const int g = lane >> 2, tg = lane & 3;
#pragma unroll
    for (int ni = 0; ni < 8; ni++) {
        int col = wc * 64 + ni * 8 + tg * 2;
        float2 bv = *(const float2*)&bias[col];
#pragma unroll
        for (int mi = 0; mi < 2; mi++) {
            int rl = wr * 32 + mi * 16 + g;
#pragma unroll
            for (int hrow = 0; hrow < 2; hrow++) {
                int r = rl + hrow * 8;
                if (r >= valid) continue;
                float v0 = c[mi][ni][hrow * 2 + 0] + bv.x;
                float v1 = c[mi][ni][hrow * 2 + 1] + bv.y;
                if (RELU) { v0 = fmaxf(v0, 0.f); v1 = fmaxf(v1, 0.f); }
                size_t grow = (size_t)(row0 + r);
                if (LAYER == 1) {
                    *(uint32_t*)&g_A2[grow * 256 + 128 + col] = pack_h2(v0, v1);
                } else {
                    float2 o; o.x = v0; o.y = v1;
                    *(float2*)&out_ext[grow * 128 + col] = o;
                }
            }
        }
    }
}

// ==================== entry point ====================
extern "C" void kernel_launch(void* const* d_in, const int* in_sizes, int n_in,
                              void* d_out, int out_size)
{
    (void)n_in; (void)out_size;
    const float* x   = (const float*)d_in[0];
    const void*  ei  = d_in[1];
    const float* W1l = (const float*)d_in[2];
    const float* W1r = (const float*)d_in[3];
    const float* b1  = (const float*)d_in[4];
    const float* W2l = (const float*)d_in[5];
    const float* W2r = (const float*)d_in[6];
    const float* b2  = (const float*)d_in[7];
    float*       out = (float*)d_out;

    int E = in_sizes[1] / 2;
    if (E > E_MAX) E = E_MAX;

    const int agg_blocks  = (N_NODES * 32 + 255) / 256;   // warp per node
    const int gemm_blocks = (N_NODES + 127) / 128;        // 782

    init_kernel<<<(N_NODES + 255) / 256, 256>>>((const int*)ei, in_sizes[1],
                                                W1l, W1r, W2l, W2r);       // 0
    hist_kernel<<<(E + 255) / 256, 256>>>(ei, E);                           // 1
    scan_part_kernel<<<NPART, 1024>>>();                                    // 2
    scan_add_kernel<<<NPART, 1024>>>();                                     // 3
    scatter_kernel<<<(E + 255) / 256, 256>>>(ei, E);                        // 4
    agg1_kernel<<<agg_blocks, 256>>>(x);                                    // 5
    gemm_fp16_kernel<128, true, 1><<<gemm_blocks, 256>>>(b1, nullptr);      // 6
    agg2_kernel<<<agg_blocks, 256>>>();                                     // 7
    gemm_fp16_kernel<256, false, 2><<<gemm_blocks, 256>>>(b2, out);         // 8
}

// round 9
// speedup vs baseline: 1.5686x; 1.0286x over previous
#include <cuda_runtime.h>
#include <cuda_fp16.h>
#include <cstdint>

#define N_NODES 100000
#define E_MAX   1600000
#define NPART   98          // ceil(100000/1024)
#define XQUADS  (N_NODES * 16)   // x as float4: 100000*64/4 = 1.6M

// ---------------- device scratch (static; no dynamic allocation) ----------------
__device__ int    g_is64;
__device__ int    g_deg[N_NODES];
__device__ int    g_offs[N_NODES + 1];
__device__ int    g_cursor[N_NODES];
__device__ int    g_part[NPART];
__device__ int    g_dst32[E_MAX];
__device__ int    g_src_sorted[E_MAX];
__device__ __half g_x16[(size_t)N_NODES * 64];    // fp16 copy of x
// fp16 operands:  A1 = [agg1 | x] (stride 128),  A2 = [agg2 | h] (stride 256)
__device__ __half g_A1[(size_t)N_NODES * 128];
__device__ __half g_A2[(size_t)N_NODES * 256];
__device__ __half g_w1[128 * 128];    // [n][k] concat(W1l, W1r)
__device__ __half g_w2[128 * 256];    // [n][k] concat(W2l, W2r)

// ==================== PTX helpers (family-portable) ====================
__device__ __forceinline__ uint32_t smem_u32(const void* p) {
    uint32_t a;
    asm("{ .reg .u64 t; cvta.to.shared.u64 t, %1; cvt.u32.u64 %0, t; }" : "=r"(a) : "l"(p));
    return a;
}
#define LDSM_X4(r0, r1, r2, r3, addr)                                           \
    asm volatile("ldmatrix.sync.aligned.m8n8.x4.shared.b16 {%0,%1,%2,%3}, [%4];" \
                 : "=r"(r0), "=r"(r1), "=r"(r2), "=r"(r3) : "r"(addr))
#define MMA16816F(c, a, b)                                                       \
    asm volatile("mma.sync.aligned.m16n8k16.row.col.f32.f16.f16.f32 "            \
                 "{%0,%1,%2,%3}, {%4,%5,%6,%7}, {%8,%9}, {%0,%1,%2,%3};"         \
                 : "+f"((c)[0]), "+f"((c)[1]), "+f"((c)[2]), "+f"((c)[3])        \
                 : "r"((a)[0]), "r"((a)[1]), "r"((a)[2]), "r"((a)[3]),           \
                   "r"((b)[0]), "r"((b)[1]))
__device__ __forceinline__ void cp16(uint32_t dst, const void* src) {
    asm volatile("cp.async.cg.shared.global [%0], [%1], 16;" :: "r"(dst), "l"(src));
}
#define CP_COMMIT() asm volatile("cp.async.commit_group;" ::: "memory")
#define CP_WAIT1()  asm volatile("cp.async.wait_group 1;" ::: "memory")
#define CP_WAIT0()  asm volatile("cp.async.wait_group 0;" ::: "memory")

__device__ __forceinline__ uint32_t pack_h2(float a, float b) {
    __half2 h = __floats2half2_rn(a, b);
    return *(uint32_t*)&h;
}

// ==================== launch 0: fused init (detect + zero + weights + x->fp16) ==
__global__ void init_kernel(const int* __restrict__ ei32, int n_words,
                            const float* __restrict__ x,
                            const float* __restrict__ W1l, const float* __restrict__ W1r,
                            const float* __restrict__ W2l, const float* __restrict__ W2r) {
    int idx = blockIdx.x * blockDim.x + threadIdx.x;
    if (blockIdx.x == 0 && threadIdx.x < 32) {
        int lane = threadIdx.x;
        int wi = 1 + 2 * lane;
        int z = (wi < n_words && ei32[wi] == 0) ? 1 : 0;
        unsigned m = __ballot_sync(0xffffffffu, z);
        if (lane == 0) g_is64 = (__popc(m) > 24) ? 1 : 0;
    }
    if (idx < N_NODES) g_deg[idx] = 0;
    if (idx < 128 * 128) {                       // layer 1 weights: Ktot=128, Kh=64
        int n = idx >> 7, k = idx & 127;
        float v = (k < 64) ? W1l[n * 64 + k] : W1r[n * 64 + (k - 64)];
        g_w1[idx] = __float2half_rn(v);
    } else if (idx < 128 * 128 + 128 * 256) {    // layer 2 weights: Ktot=256, Kh=128
        int j = idx - 128 * 128;
        int n = j >> 8, k = j & 255;
        float v = (k < 128) ? W2l[n * 128 + k] : W2r[n * 128 + (k - 128)];
        g_w2[j] = __float2half_rn(v);
    }
    if (idx < XQUADS) {                          // x -> fp16 (per float4)
        float4 v = *(const float4*)&x[(size_t)idx * 4];
        uint2 o;
        o.x = pack_h2(v.x, v.y);
        o.y = pack_h2(v.z, v.w);
        *(uint2*)&g_x16[(size_t)idx * 4] = o;
    }
}

// ==================== CSR build ====================
__device__ __forceinline__ int load_idx(const void* ei, size_t pos) {
    if (g_is64) return (int)((const long long*)ei)[pos];
    return ((const int*)ei)[pos];
}
__global__ void hist_kernel(const void* __restrict__ ei, int E) {
    int e = blockIdx.x * blockDim.x + threadIdx.x;
    if (e < E) {
        int d = load_idx(ei, (size_t)E + e);
        g_dst32[e] = d;
        if ((unsigned)d < (unsigned)N_NODES) atomicAdd(&g_deg[d], 1);
    }
}
__global__ void scan_part_kernel() {
    __shared__ int s_woff[32];
    int tid = threadIdx.x, lane = tid & 31, wid = tid >> 5;
    int i = blockIdx.x * 1024 + tid;
    int v = (i < N_NODES) ? g_deg[i] : 0;
    int inc = v;
#pragma unroll
    for (int o = 1; o < 32; o <<= 1) {
        int t = __shfl_up_sync(0xffffffffu, inc, o);
        if (lane >= o) inc += t;
    }
    if (lane == 31) s_woff[wid] = inc;
    __syncthreads();
    if (wid == 0) {
        int ws = s_woff[lane];
        int wi = ws;
#pragma unroll
        for (int o = 1; o < 32; o <<= 1) {
            int t = __shfl_up_sync(0xffffffffu, wi, o);
            if (lane >= o) wi += t;
        }
        s_woff[lane] = wi - ws;
    }
    __syncthreads();
    int excl = s_woff[wid] + inc - v;
    if (i < N_NODES) g_offs[i] = excl;
    if (tid == 1023) g_part[blockIdx.x] = excl + v;
}
__global__ void scan_add_kernel() {     // each block self-computes its prefix over 98 partials
    __shared__ int redA[32], redB[32];
    __shared__ int s_off, s_tot;
    int tid = threadIdx.x, lane = tid & 31, wid = tid >> 5;
    int p  = (tid < NPART) ? g_part[tid] : 0;
    int v1 = (tid < (int)blockIdx.x) ? p : 0;
    int v2 = p;
#pragma unroll
    for (int o = 16; o > 0; o >>= 1) {
        v1 += __shfl_xor_sync(0xffffffffu, v1, o);
        v2 += __shfl_xor_sync(0xffffffffu, v2, o);
    }
    if (lane == 0) { redA[wid] = v1; redB[wid] = v2; }
    __syncthreads();
    if (wid == 0) {
        int a = redA[lane], b = redB[lane];
#pragma unroll
        for (int o = 16; o > 0; o >>= 1) {
            a += __shfl_xor_sync(0xffffffffu, a, o);
            b += __shfl_xor_sync(0xffffffffu, b, o);
        }
        if (lane == 0) { s_off = a; s_tot = b; }
    }
    __syncthreads();
    int i = blockIdx.x * 1024 + tid;
    if (i < N_NODES) {
        int o = g_offs[i] + s_off;
        g_offs[i] = o;
        g_cursor[i] = o;
    }
    if (blockIdx.x == NPART - 1 && tid == 0) g_offs[N_NODES] = s_tot;
}
__global__ void scatter_kernel(const void* __restrict__ ei, int E) {
    int e = blockIdx.x * blockDim.x + threadIdx.x;
    if (e < E) {
        int d = g_dst32[e];
        int s = load_idx(ei, (size_t)e);
        if ((unsigned)d < (unsigned)N_NODES && (unsigned)s < (unsigned)N_NODES) {
            int p = atomicAdd(&g_cursor[d], 1);
            g_src_sorted[p] = s;
        }
    }
}

// ==================== fused aggregation (warp per node, fp16 gathers) ===========
// layer 1: A1 = [ mean(x16 nbrs) | x16 ]
__global__ void agg1_kernel() {
    int w = (blockIdx.x * blockDim.x + threadIdx.x) >> 5;
    if (w >= N_NODES) return;
    int lane = threadIdx.x & 31;
    int beg = g_offs[w], end = g_offs[w + 1];
    float inv = 1.0f / (float)max(end - beg, 1);
    float ax = 0.f, ay = 0.f;
    for (int eb = beg; eb < end; eb += 32) {
        int n = min(32, end - eb);
        int s = (lane < n) ? g_src_sorted[eb + lane] : 0;
        for (int t = 0; t < n; t++) {
            int ss = __shfl_sync(0xffffffffu, s, t);
            uint32_t p = *(const uint32_t*)&g_x16[(size_t)ss * 64 + lane * 2];
            float2 f = __half22float2(*(__half2*)&p);
            ax += f.x; ay += f.y;
        }
    }
    size_t base = (size_t)w * 128 + lane * 2;
    *(uint32_t*)&g_A1[base] = pack_h2(ax * inv, ay * inv);
    // self part: straight fp16 copy
    *(uint32_t*)&g_A1[base + 64] = *(const uint32_t*)&g_x16[(size_t)w * 64 + lane * 2];
}
// layer 2: A2 cols 0..127 = mean of h-fp16 (cols 128..255, written by gemm1 epilogue)
__global__ void agg2_kernel() {
    int w = (blockIdx.x * blockDim.x + threadIdx.x) >> 5;
    if (w >= N_NODES) return;
    int lane = threadIdx.x & 31;
    int beg = g_offs[w], end = g_offs[w + 1];
    float inv = 1.0f / (float)max(end - beg, 1);
    float ax = 0.f, ay = 0.f, az = 0.f, aw = 0.f;
    for (int eb = beg; eb < end; eb += 32) {
        int n = min(32, end - eb);
        int s = (lane < n) ? g_src_sorted[eb + lane] : 0;
        for (int t = 0; t < n; t++) {
            int ss = __shfl_sync(0xffffffffu, s, t);
            uint2 p = *(const uint2*)&g_A2[(size_t)ss * 256 + 128 + lane * 4];
            float2 f0 = __half22float2(*(__half2*)&p.x);
            float2 f1 = __half22float2(*(__half2*)&p.y);
            ax += f0.x; ay += f0.y; az += f1.x; aw += f1.y;
        }
    }
    uint2 o;
    o.x = pack_h2(ax * inv, ay * inv);
    o.y = pack_h2(az * inv, aw * inv);
    *(uint2*)&g_A2[(size_t)w * 256 + lane * 4] = o;
}

// ==================== cp.async pipelined fp16 mma GEMM (BK=32) ====================
// CTA 128x128, BK=32 halves, 2-stage double buffer, RS=40 halves (80B rows —
// round-4-validated conflict-free layout: banks r*20 mod 32 distinct).
// 8 warps, warp tile m32 x n64, 32 MMAs per chunk-warp.
template <int KT, bool RELU, int LAYER>
__global__ __launch_bounds__(256) void gemm_fp16_kernel(
    const float* __restrict__ bias, float* __restrict__ out_ext)
{
    constexpr int NCH = KT / 32;
    constexpr int RS = 40;
    constexpr uint32_t ARR_B = 128 * RS * 2;      // 10240 B per array
    constexpr uint32_t STG_B = 2 * ARR_B;         // A + W per stage
    __shared__ __align__(16) __half sbuf[2][2][128 * RS];   // 40 KB

    const __half* A = (LAYER == 1) ? g_A1 : g_A2;
    const __half* W = (LAYER == 1) ? g_w1 : g_w2;

    const int tid = threadIdx.x, lane = tid & 31, wid = tid >> 5;
    const int row0 = blockIdx.x * 128;
    const int valid = min(128, N_NODES - row0);
    const int wr = wid & 3, wc = wid >> 2;

    float c[2][8][4];
#pragma unroll
    for (int mi = 0; mi < 2; mi++)
#pragma unroll
        for (int ni = 0; ni < 8; ni++)
#pragma unroll
            for (int q = 0; q < 4; q++) c[mi][ni][q] = 0.f;

    const uint32_t sb0 = smem_u32(sbuf);

    // cp.async mapping: 128 rows x 4 16B-units; each thread: 2 units A + 2 units W
    const int ld_r = tid >> 1;
    const int ld_u = (tid & 1) * 2;
    const int ar = min(row0 + ld_r, N_NODES - 1);
    const size_t goA = (size_t)ar * KT + ld_u * 8;
    const size_t goW = (size_t)ld_r * KT + ld_u * 8;
    const uint32_t dst_ru = (uint32_t)(ld_r * RS + ld_u * 8) * 2;

    const int a_m = ((lane >> 3) & 1) * 8 + (lane & 7);
    const int a_u = (lane >> 4);
    const int b_n = ((lane >> 4) << 3) + (lane & 7);
    const int b_u = ((lane >> 3) & 1);

    {
        uint32_t d = sb0 + dst_ru;
        cp16(d, &A[goA]);            cp16(d + 16, &A[goA + 8]);
        cp16(d + ARR_B, &W[goW]);    cp16(d + ARR_B + 16, &W[goW + 8]);
        CP_COMMIT();
    }

    for (int kc = 0; kc < NCH; kc++) {
        if (kc + 1 < NCH) {
            uint32_t d = sb0 + ((kc + 1) & 1) * STG_B + dst_ru;
            size_t ko = (size_t)(kc + 1) * 32;
            cp16(d, &A[goA + ko]);            cp16(d + 16, &A[goA + ko + 8]);
            cp16(d + ARR_B, &W[goW + ko]);    cp16(d + ARR_B + 16, &W[goW + ko + 8]);
            CP_COMMIT();
            CP_WAIT1();
        } else {
            CP_WAIT0();
        }
        __syncthreads();

        const uint32_t sa = sb0 + (kc & 1) * STG_B;
        const uint32_t sw = sa + ARR_B;

#pragma unroll
        for (int ks = 0; ks < 2; ks++) {
            uint32_t af[2][4], bf[8][2];
#pragma unroll
            for (int mi = 0; mi < 2; mi++) {
                int rr = wr * 32 + mi * 16 + a_m;
                uint32_t off = (uint32_t)(rr * RS + (ks * 2 + a_u) * 8) * 2;
                LDSM_X4(af[mi][0], af[mi][1], af[mi][2], af[mi][3], sa + off);
            }
#pragma unroll
            for (int nj = 0; nj < 4; nj++) {
                int nr = wc * 64 + nj * 16 + b_n;
                uint32_t off = (uint32_t)(nr * RS + (ks * 2 + b_u) * 8) * 2;
                LDSM_X4(bf[nj * 2][0], bf[nj * 2][1], bf[nj * 2 + 1][0], bf[nj * 2 + 1][1], sw + off);
            }
#pragma unroll
            for (int mi = 0; mi < 2; mi++)
#pragma unroll
                for (int ni = 0; ni < 8; ni++)
                    MMA16816F(c[mi][ni], af[mi], bf[ni]);
        }
        __syncthreads();
    }

    // ---- epilogue: bias + (relu); layer1 -> h (fp16) into A2 cols 128..255 ----
    const int g = lane >> 2, tg = lane & 3;
#pragma unroll
    for (int ni = 0; ni < 8; ni++) {
        int col = wc * 64 + ni * 8 + tg * 2;
        float2 bv = *(const float2*)&bias[col];
#pragma unroll
        for (int mi = 0; mi < 2; mi++) {
            int rl = wr * 32 + mi * 16 + g;
#pragma unroll
            for (int hrow = 0; hrow < 2; hrow++) {
                int r = rl + hrow * 8;
                if (r >= valid) continue;
                float v0 = c[mi][ni][hrow * 2 + 0] + bv.x;
                float v1 = c[mi][ni][hrow * 2 + 1] + bv.y;
                if (RELU) { v0 = fmaxf(v0, 0.f); v1 = fmaxf(v1, 0.f); }
                size_t grow = (size_t)(row0 + r);
                if (LAYER == 1) {
                    *(uint32_t*)&g_A2[grow * 256 + 128 + col] = pack_h2(v0, v1);
                } else {
                    float2 o; o.x = v0; o.y = v1;
                    *(float2*)&out_ext[grow * 128 + col] = o;
                }
            }
        }
    }
}

// ==================== entry point ====================
extern "C" void kernel_launch(void* const* d_in, const int* in_sizes, int n_in,
                              void* d_out, int out_size)
{
    (void)n_in; (void)out_size;
    const float* x   = (const float*)d_in[0];
    const void*  ei  = d_in[1];
    const float* W1l = (const float*)d_in[2];
    const float* W1r = (const float*)d_in[3];
    const float* b1  = (const float*)d_in[4];
    const float* W2l = (const float*)d_in[5];
    const float* W2r = (const float*)d_in[6];
    const float* b2  = (const float*)d_in[7];
    float*       out = (float*)d_out;

    int E = in_sizes[1] / 2;
    if (E > E_MAX) E = E_MAX;

    const int agg_blocks  = (N_NODES * 32 + 255) / 256;   // warp per node
    const int gemm_blocks = (N_NODES + 127) / 128;        // 782

    init_kernel<<<(XQUADS + 255) / 256, 256>>>((const int*)ei, in_sizes[1], x,
                                               W1l, W1r, W2l, W2r);        // 0
    hist_kernel<<<(E + 255) / 256, 256>>>(ei, E);                           // 1
    scan_part_kernel<<<NPART, 1024>>>();                                    // 2
    scan_add_kernel<<<NPART, 1024>>>();                                     // 3
    scatter_kernel<<<(E + 255) / 256, 256>>>(ei, E);                        // 4
    agg1_kernel<<<agg_blocks, 256>>>();                                     // 5
    gemm_fp16_kernel<128, true, 1><<<gemm_blocks, 256>>>(b1, nullptr);      // 6
    agg2_kernel<<<agg_blocks, 256>>>();                                     // 7
    gemm_fp16_kernel<256, false, 2><<<gemm_blocks, 256>>>(b2, out);         // 8
}

// round 10
// speedup vs baseline: 1.6308x; 1.0397x over previous
#include <cuda_runtime.h>
#include <cuda_fp16.h>
#include <cstdint>

#define N_NODES 100000
#define E_MAX   1600000
#define NPART   98          // ceil(100000/1024)
#define XQUADS  (N_NODES * 16)   // x as float4: 100000*64/4 = 1.6M

// ---------------- device scratch (static; no dynamic allocation) ----------------
__device__ int    g_is64;
__device__ int    g_deg[N_NODES];
__device__ int    g_offs[N_NODES + 1];
__device__ int    g_cursor[N_NODES];
__device__ int    g_part[NPART];
__device__ int    g_dst32[E_MAX];
__device__ int    g_src_sorted[E_MAX];
__device__ __half g_x16[(size_t)N_NODES * 64];    // fp16 copy of x
// fp16 operands:  A1 = [agg1 | x] (stride 128),  A2 = [agg2 | h] (stride 256)
__device__ __half g_A1[(size_t)N_NODES * 128];
__device__ __half g_A2[(size_t)N_NODES * 256];
__device__ __half g_w1[128 * 128];    // [n][k] concat(W1l, W1r)
__device__ __half g_w2[128 * 256];    // [n][k] concat(W2l, W2r)

// ==================== PTX helpers (family-portable) ====================
__device__ __forceinline__ uint32_t smem_u32(const void* p) {
    uint32_t a;
    asm("{ .reg .u64 t; cvta.to.shared.u64 t, %1; cvt.u32.u64 %0, t; }" : "=r"(a) : "l"(p));
    return a;
}
#define LDSM_X4(r0, r1, r2, r3, addr)                                           \
    asm volatile("ldmatrix.sync.aligned.m8n8.x4.shared.b16 {%0,%1,%2,%3}, [%4];" \
                 : "=r"(r0), "=r"(r1), "=r"(r2), "=r"(r3) : "r"(addr))
#define MMA16816F(c, a, b)                                                       \
    asm volatile("mma.sync.aligned.m16n8k16.row.col.f32.f16.f16.f32 "            \
                 "{%0,%1,%2,%3}, {%4,%5,%6,%7}, {%8,%9}, {%0,%1,%2,%3};"         \
                 : "+f"((c)[0]), "+f"((c)[1]), "+f"((c)[2]), "+f"((c)[3])        \
                 : "r"((a)[0]), "r"((a)[1]), "r"((a)[2]), "r"((a)[3]),           \
                   "r"((b)[0]), "r"((b)[1]))
__device__ __forceinline__ void cp16(uint32_t dst, const void* src) {
    asm volatile("cp.async.cg.shared.global [%0], [%1], 16;" :: "r"(dst), "l"(src));
}
#define CP_COMMIT() asm volatile("cp.async.commit_group;" ::: "memory")
#define CP_WAIT1()  asm volatile("cp.async.wait_group 1;" ::: "memory")
#define CP_WAIT0()  asm volatile("cp.async.wait_group 0;" ::: "memory")

__device__ __forceinline__ uint32_t pack_h2(float a, float b) {
    __half2 h = __floats2half2_rn(a, b);
    return *(uint32_t*)&h;
}
// accumulate 8 halves (uint4) into 8 fp32 accumulators
__device__ __forceinline__ void acc8(const uint4& p, float* a) {
    float2 f0 = __half22float2(*(const __half2*)&p.x);
    float2 f1 = __half22float2(*(const __half2*)&p.y);
    float2 f2 = __half22float2(*(const __half2*)&p.z);
    float2 f3 = __half22float2(*(const __half2*)&p.w);
    a[0] += f0.x; a[1] += f0.y; a[2] += f1.x; a[3] += f1.y;
    a[4] += f2.x; a[5] += f2.y; a[6] += f3.x; a[7] += f3.y;
}

// ==================== launch 0: fused init (detect + zero + weights + x->fp16) ==
__global__ void init_kernel(const int* __restrict__ ei32, int n_words,
                            const float* __restrict__ x,
                            const float* __restrict__ W1l, const float* __restrict__ W1r,
                            const float* __restrict__ W2l, const float* __restrict__ W2r) {
    int idx = blockIdx.x * blockDim.x + threadIdx.x;
    if (blockIdx.x == 0 && threadIdx.x < 32) {
        int lane = threadIdx.x;
        int wi = 1 + 2 * lane;
        int z = (wi < n_words && ei32[wi] == 0) ? 1 : 0;
        unsigned m = __ballot_sync(0xffffffffu, z);
        if (lane == 0) g_is64 = (__popc(m) > 24) ? 1 : 0;
    }
    if (idx < N_NODES) g_deg[idx] = 0;
    if (idx < 128 * 128) {                       // layer 1 weights: Ktot=128, Kh=64
        int n = idx >> 7, k = idx & 127;
        float v = (k < 64) ? W1l[n * 64 + k] : W1r[n * 64 + (k - 64)];
        g_w1[idx] = __float2half_rn(v);
    } else if (idx < 128 * 128 + 128 * 256) {    // layer 2 weights: Ktot=256, Kh=128
        int j = idx - 128 * 128;
        int n = j >> 8, k = j & 255;
        float v = (k < 128) ? W2l[n * 128 + k] : W2r[n * 128 + (k - 128)];
        g_w2[j] = __float2half_rn(v);
    }
    if (idx < XQUADS) {                          // x -> fp16 (per float4)
        float4 v = *(const float4*)&x[(size_t)idx * 4];
        uint2 o;
        o.x = pack_h2(v.x, v.y);
        o.y = pack_h2(v.z, v.w);
        *(uint2*)&g_x16[(size_t)idx * 4] = o;
    }
}

// ==================== CSR build ====================
__device__ __forceinline__ int load_idx(const void* ei, size_t pos) {
    if (g_is64) return (int)((const long long*)ei)[pos];
    return ((const int*)ei)[pos];
}
__global__ void hist_kernel(const void* __restrict__ ei, int E) {
    int e = blockIdx.x * blockDim.x + threadIdx.x;
    if (e < E) {
        int d = load_idx(ei, (size_t)E + e);
        g_dst32[e] = d;
        if ((unsigned)d < (unsigned)N_NODES) atomicAdd(&g_deg[d], 1);
    }
}
__global__ void scan_part_kernel() {
    __shared__ int s_woff[32];
    int tid = threadIdx.x, lane = tid & 31, wid = tid >> 5;
    int i = blockIdx.x * 1024 + tid;
    int v = (i < N_NODES) ? g_deg[i] : 0;
    int inc = v;
#pragma unroll
    for (int o = 1; o < 32; o <<= 1) {
        int t = __shfl_up_sync(0xffffffffu, inc, o);
        if (lane >= o) inc += t;
    }
    if (lane == 31) s_woff[wid] = inc;
    __syncthreads();
    if (wid == 0) {
        int ws = s_woff[lane];
        int wi = ws;
#pragma unroll
        for (int o = 1; o < 32; o <<= 1) {
            int t = __shfl_up_sync(0xffffffffu, wi, o);
            if (lane >= o) wi += t;
        }
        s_woff[lane] = wi - ws;
    }
    __syncthreads();
    int excl = s_woff[wid] + inc - v;
    if (i < N_NODES) g_offs[i] = excl;
    if (tid == 1023) g_part[blockIdx.x] = excl + v;
}
__global__ void scan_add_kernel() {     // each block self-computes its prefix over 98 partials
    __shared__ int redA[32], redB[32];
    __shared__ int s_off, s_tot;
    int tid = threadIdx.x, lane = tid & 31, wid = tid >> 5;
    int p  = (tid < NPART) ? g_part[tid] : 0;
    int v1 = (tid < (int)blockIdx.x) ? p : 0;
    int v2 = p;
#pragma unroll
    for (int o = 16; o > 0; o >>= 1) {
        v1 += __shfl_xor_sync(0xffffffffu, v1, o);
        v2 += __shfl_xor_sync(0xffffffffu, v2, o);
    }
    if (lane == 0) { redA[wid] = v1; redB[wid] = v2; }
    __syncthreads();
    if (wid == 0) {
        int a = redA[lane], b = redB[lane];
#pragma unroll
        for (int o = 16; o > 0; o >>= 1) {
            a += __shfl_xor_sync(0xffffffffu, a, o);
            b += __shfl_xor_sync(0xffffffffu, b, o);
        }
        if (lane == 0) { s_off = a; s_tot = b; }
    }
    __syncthreads();
    int i = blockIdx.x * 1024 + tid;
    if (i < N_NODES) {
        int o = g_offs[i] + s_off;
        g_offs[i] = o;
        g_cursor[i] = o;
    }
    if (blockIdx.x == NPART - 1 && tid == 0) g_offs[N_NODES] = s_tot;
}
__global__ void scatter_kernel(const void* __restrict__ ei, int E) {
    int e = blockIdx.x * blockDim.x + threadIdx.x;
    if (e < E) {
        int d = g_dst32[e];
        int s = load_idx(ei, (size_t)e);
        if ((unsigned)d < (unsigned)N_NODES && (unsigned)s < (unsigned)N_NODES) {
            int p = atomicAdd(&g_cursor[d], 1);
            g_src_sorted[p] = s;
        }
    }
}

// ==================== group-parallel aggregation ====================
// agg1: warp = 4 groups x 8 lanes; each group gathers one 128B fp16 row per iter.
// lane's 16B unit = features (lane&7)*8 .. +8. Cross-group reduce at the end.
__global__ void agg1_kernel() {
    int w = (blockIdx.x * blockDim.x + threadIdx.x) >> 5;
    if (w >= N_NODES) return;
    int lane = threadIdx.x & 31;
    int grp = lane >> 3, gl = lane & 7;
    int beg = g_offs[w], end = g_offs[w + 1];
    float inv = 1.0f / (float)max(end - beg, 1);
    float a[8] = {0.f, 0.f, 0.f, 0.f, 0.f, 0.f, 0.f, 0.f};
    for (int e = beg + grp; e < end; e += 4) {
        int ss = g_src_sorted[e];                       // 8-lane broadcast load
        uint4 p = *(const uint4*)&g_x16[(size_t)ss * 64 + gl * 8];
        acc8(p, a);
    }
#pragma unroll
    for (int f = 0; f < 8; f++) {
        a[f] += __shfl_xor_sync(0xffffffffu, a[f], 8);
        a[f] += __shfl_xor_sync(0xffffffffu, a[f], 16);
    }
    if (lane < 8) {
        uint4 o;
        o.x = pack_h2(a[0] * inv, a[1] * inv);
        o.y = pack_h2(a[2] * inv, a[3] * inv);
        o.z = pack_h2(a[4] * inv, a[5] * inv);
        o.w = pack_h2(a[6] * inv, a[7] * inv);
        *(uint4*)&g_A1[(size_t)w * 128 + lane * 8] = o;
    }
    // self part (cols 64..127): straight fp16 copy, all 32 lanes (4B each)
    *(uint32_t*)&g_A1[(size_t)w * 128 + 64 + lane * 2] =
        *(const uint32_t*)&g_x16[(size_t)w * 64 + lane * 2];
}
// agg2: warp = 2 groups x 16 lanes; each group gathers one 256B fp16 h-row per iter.
__global__ void agg2_kernel() {
    int w = (blockIdx.x * blockDim.x + threadIdx.x) >> 5;
    if (w >= N_NODES) return;
    int lane = threadIdx.x & 31;
    int grp = lane >> 4, gl = lane & 15;
    int beg = g_offs[w], end = g_offs[w + 1];
    float inv = 1.0f / (float)max(end - beg, 1);
    float a[8] = {0.f, 0.f, 0.f, 0.f, 0.f, 0.f, 0.f, 0.f};
    for (int e = beg + grp; e < end; e += 2) {
        int ss = g_src_sorted[e];                       // 16-lane broadcast load
        uint4 p = *(const uint4*)&g_A2[(size_t)ss * 256 + 128 + gl * 8];
        acc8(p, a);
    }
#pragma unroll
    for (int f = 0; f < 8; f++)
        a[f] += __shfl_xor_sync(0xffffffffu, a[f], 16);
    if (lane < 16) {
        uint4 o;
        o.x = pack_h2(a[0] * inv, a[1] * inv);
        o.y = pack_h2(a[2] * inv, a[3] * inv);
        o.z = pack_h2(a[4] * inv, a[5] * inv);
        o.w = pack_h2(a[6] * inv, a[7] * inv);
        *(uint4*)&g_A2[(size_t)w * 256 + lane * 8] = o;
    }
}

// ==================== cp.async pipelined fp16 mma GEMM (BK=32) ====================
// CTA 128x128, BK=32 halves, 2-stage double buffer, RS=40 halves (80B rows —
// validated conflict-free layout). 8 warps, warp tile m32 x n64.
template <int KT, bool RELU, int LAYER>
__global__ __launch_bounds__(256) void gemm_fp16_kernel(
    const float* __restrict__ bias, float* __restrict__ out_ext)
{
    constexpr int NCH = KT / 32;
    constexpr int RS = 40;
    constexpr uint32_t ARR_B = 128 * RS * 2;      // 10240 B per array
    constexpr uint32_t STG_B = 2 * ARR_B;         // A + W per stage
    __shared__ __align__(16) __half sbuf[2][2][128 * RS];   // 40 KB

    const __half* A = (LAYER == 1) ? g_A1 : g_A2;
    const __half* W = (LAYER == 1) ? g_w1 : g_w2;

    const int tid = threadIdx.x, lane = tid & 31, wid = tid >> 5;
    const int row0 = blockIdx.x * 128;
    const int valid = min(128, N_NODES - row0);
    const int wr = wid & 3, wc = wid >> 2;

    float c[2][8][4];
#pragma unroll
    for (int mi = 0; mi < 2; mi++)
#pragma unroll
        for (int ni = 0; ni < 8; ni++)
#pragma unroll
            for (int q = 0; q < 4; q++) c[mi][ni][q] = 0.f;

    const uint32_t sb0 = smem_u32(sbuf);

    const int ld_r = tid >> 1;
    const int ld_u = (tid & 1) * 2;
    const int ar = min(row0 + ld_r, N_NODES - 1);
    const size_t goA = (size_t)ar * KT + ld_u * 8;
    const size_t goW = (size_t)ld_r * KT + ld_u * 8;
    const uint32_t dst_ru = (uint32_t)(ld_r * RS + ld_u * 8) * 2;

    const int a_m = ((lane >> 3) & 1) * 8 + (lane & 7);
    const int a_u = (lane >> 4);
    const int b_n = ((lane >> 4) << 3) + (lane & 7);
    const int b_u = ((lane >> 3) & 1);

    {
        uint32_t d = sb0 + dst_ru;
        cp16(d, &A[goA]);            cp16(d + 16, &A[goA + 8]);
        cp16(d + ARR_B, &W[goW]);    cp16(d + ARR_B + 16, &W[goW + 8]);
        CP_COMMIT();
    }

    for (int kc = 0; kc < NCH; kc++) {
        if (kc + 1 < NCH) {
            uint32_t d = sb0 + ((kc + 1) & 1) * STG_B + dst_ru;
            size_t ko = (size_t)(kc + 1) * 32;
            cp16(d, &A[goA + ko]);            cp16(d + 16, &A[goA + ko + 8]);
            cp16(d + ARR_B, &W[goW + ko]);    cp16(d + ARR_B + 16, &W[goW + ko + 8]);
            CP_COMMIT();
            CP_WAIT1();
        } else {
            CP_WAIT0();
        }
        __syncthreads();

        const uint32_t sa = sb0 + (kc & 1) * STG_B;
        const uint32_t sw = sa + ARR_B;

#pragma unroll
        for (int ks = 0; ks < 2; ks++) {
            uint32_t af[2][4], bf[8][2];
#pragma unroll
            for (int mi = 0; mi < 2; mi++) {
                int rr = wr * 32 + mi * 16 + a_m;
                uint32_t off = (uint32_t)(rr * RS + (ks * 2 + a_u) * 8) * 2;
                LDSM_X4(af[mi][0], af[mi][1], af[mi][2], af[mi][3], sa + off);
            }
#pragma unroll
            for (int nj = 0; nj < 4; nj++) {
                int nr = wc * 64 + nj * 16 + b_n;
                uint32_t off = (uint32_t)(nr * RS + (ks * 2 + b_u) * 8) * 2;
                LDSM_X4(bf[nj * 2][0], bf[nj * 2][1], bf[nj * 2 + 1][0], bf[nj * 2 + 1][1], sw + off);
            }
#pragma unroll
            for (int mi = 0; mi < 2; mi++)
#pragma unroll
                for (int ni = 0; ni < 8; ni++)
                    MMA16816F(c[mi][ni], af[mi], bf[ni]);
        }
        __syncthreads();
    }

    // ---- epilogue: bias + (relu); layer1 -> h (fp16) into A2 cols 128..255 ----
    const int g = lane >> 2, tg = lane & 3;
#pragma unroll
    for (int ni = 0; ni < 8; ni++) {
        int col = wc * 64 + ni * 8 + tg * 2;
        float2 bv = *(const float2*)&bias[col];
#pragma unroll
        for (int mi = 0; mi < 2; mi++) {
            int rl = wr * 32 + mi * 16 + g;
#pragma unroll
            for (int hrow = 0; hrow < 2; hrow++) {
                int r = rl + hrow * 8;
                if (r >= valid) continue;
                float v0 = c[mi][ni][hrow * 2 + 0] + bv.x;
                float v1 = c[mi][ni][hrow * 2 + 1] + bv.y;
                if (RELU) { v0 = fmaxf(v0, 0.f); v1 = fmaxf(v1, 0.f); }
                size_t grow = (size_t)(row0 + r);
                if (LAYER == 1) {
                    *(uint32_t*)&g_A2[grow * 256 + 128 + col] = pack_h2(v0, v1);
                } else {
                    float2 o; o.x = v0; o.y = v1;
                    *(float2*)&out_ext[grow * 128 + col] = o;
                }
            }
        }
    }
}

// ==================== entry point ====================
extern "C" void kernel_launch(void* const* d_in, const int* in_sizes, int n_in,
                              void* d_out, int out_size)
{
    (void)n_in; (void)out_size;
    const float* x   = (const float*)d_in[0];
    const void*  ei  = d_in[1];
    const float* W1l = (const float*)d_in[2];
    const float* W1r = (const float*)d_in[3];
    const float* b1  = (const float*)d_in[4];
    const float* W2l = (const float*)d_in[5];
    const float* W2r = (const float*)d_in[6];
    const float* b2  = (const float*)d_in[7];
    float*       out = (float*)d_out;

    int E = in_sizes[1] / 2;
    if (E > E_MAX) E = E_MAX;

    const int agg_blocks  = (N_NODES * 32 + 255) / 256;   // warp per node
    const int gemm_blocks = (N_NODES + 127) / 128;        // 782

    init_kernel<<<(XQUADS + 255) / 256, 256>>>((const int*)ei, in_sizes[1], x,
                                               W1l, W1r, W2l, W2r);        // 0
    hist_kernel<<<(E + 255) / 256, 256>>>(ei, E);                           // 1
    scan_part_kernel<<<NPART, 1024>>>();                                    // 2
    scan_add_kernel<<<NPART, 1024>>>();                                     // 3
    scatter_kernel<<<(E + 255) / 256, 256>>>(ei, E);                        // 4
    agg1_kernel<<<agg_blocks, 256>>>();                                     // 5
    gemm_fp16_kernel<128, true, 1><<<gemm_blocks, 256>>>(b1, nullptr);      // 6
    agg2_kernel<<<agg_blocks, 256>>>();                                     // 7
    gemm_fp16_kernel<256, false, 2><<<gemm_blocks, 256>>>(b2, out);         // 8
}

// round 11
// speedup vs baseline: 1.6690x; 1.0234x over previous
#include <cuda_runtime.h>
#include <cuda_fp16.h>
#include <cstdint>

#define N_NODES 100000
#define E_MAX   1600000
#define NPART   98          // ceil(100000/1024)
#define XQUADS  (N_NODES * 16)   // x as float4: 100000*64/4 = 1.6M

// ---------------- device scratch (static; no dynamic allocation) ----------------
__device__ int    g_is64;
__device__ int    g_deg[N_NODES];
__device__ int    g_offs[N_NODES + 1];
__device__ int    g_cursor[N_NODES];
__device__ int    g_part[NPART];
__device__ int    g_src_sorted[E_MAX];
__device__ __half g_x16[(size_t)N_NODES * 64];    // fp16 copy of x
// fp16 operands:  A1 = [agg1 | x] (stride 128),  A2 = [agg2 | h] (stride 256)
__device__ __half g_A1[(size_t)N_NODES * 128];
__device__ __half g_A2[(size_t)N_NODES * 256];
__device__ __half g_w1[128 * 128];    // [n][k] concat(W1l, W1r)
__device__ __half g_w2[128 * 256];    // [n][k] concat(W2l, W2r)

// ==================== PTX helpers (family-portable) ====================
__device__ __forceinline__ uint32_t smem_u32(const void* p) {
    uint32_t a;
    asm("{ .reg .u64 t; cvta.to.shared.u64 t, %1; cvt.u32.u64 %0, t; }" : "=r"(a) : "l"(p));
    return a;
}
#define LDSM_X4(r0, r1, r2, r3, addr)                                           \
    asm volatile("ldmatrix.sync.aligned.m8n8.x4.shared.b16 {%0,%1,%2,%3}, [%4];" \
                 : "=r"(r0), "=r"(r1), "=r"(r2), "=r"(r3) : "r"(addr))
#define MMA16816F(c, a, b)                                                       \
    asm volatile("mma.sync.aligned.m16n8k16.row.col.f32.f16.f16.f32 "            \
                 "{%0,%1,%2,%3}, {%4,%5,%6,%7}, {%8,%9}, {%0,%1,%2,%3};"         \
                 : "+f"((c)[0]), "+f"((c)[1]), "+f"((c)[2]), "+f"((c)[3])        \
                 : "r"((a)[0]), "r"((a)[1]), "r"((a)[2]), "r"((a)[3]),           \
                   "r"((b)[0]), "r"((b)[1]))
__device__ __forceinline__ void cp16(uint32_t dst, const void* src) {
    asm volatile("cp.async.cg.shared.global [%0], [%1], 16;" :: "r"(dst), "l"(src));
}
#define CP_COMMIT() asm volatile("cp.async.commit_group;" ::: "memory")
#define CP_WAIT1()  asm volatile("cp.async.wait_group 1;" ::: "memory")
#define CP_WAIT0()  asm volatile("cp.async.wait_group 0;" ::: "memory")

__device__ __forceinline__ uint32_t pack_h2(float a, float b) {
    __half2 h = __floats2half2_rn(a, b);
    return *(uint32_t*)&h;
}
// accumulate 8 halves (uint4) into 8 fp32 accumulators
__device__ __forceinline__ void acc8(const uint4& p, float* a) {
    float2 f0 = __half22float2(*(const __half2*)&p.x);
    float2 f1 = __half22float2(*(const __half2*)&p.y);
    float2 f2 = __half22float2(*(const __half2*)&p.z);
    float2 f3 = __half22float2(*(const __half2*)&p.w);
    a[0] += f0.x; a[1] += f0.y; a[2] += f1.x; a[3] += f1.y;
    a[4] += f2.x; a[5] += f2.y; a[6] += f3.x; a[7] += f3.y;
}

// ==================== launch 0: fused init (detect + zero + weights + x->fp16) ==
__global__ void init_kernel(const int* __restrict__ ei32, int n_words,
                            const float* __restrict__ x,
                            const float* __restrict__ W1l, const float* __restrict__ W1r,
                            const float* __restrict__ W2l, const float* __restrict__ W2r) {
    int idx = blockIdx.x * blockDim.x + threadIdx.x;
    if (blockIdx.x == 0 && threadIdx.x < 32) {
        int lane = threadIdx.x;
        int wi = 1 + 2 * lane;
        int z = (wi < n_words && ei32[wi] == 0) ? 1 : 0;
        unsigned m = __ballot_sync(0xffffffffu, z);
        if (lane == 0) g_is64 = (__popc(m) > 24) ? 1 : 0;
    }
    if (idx < N_NODES) g_deg[idx] = 0;
    if (idx < 128 * 128) {                       // layer 1 weights: Ktot=128, Kh=64
        int n = idx >> 7, k = idx & 127;
        float v = (k < 64) ? W1l[n * 64 + k] : W1r[n * 64 + (k - 64)];
        g_w1[idx] = __float2half_rn(v);
    } else if (idx < 128 * 128 + 128 * 256) {    // layer 2 weights: Ktot=256, Kh=128
        int j = idx - 128 * 128;
        int n = j >> 8, k = j & 255;
        float v = (k < 128) ? W2l[n * 128 + k] : W2r[n * 128 + (k - 128)];
        g_w2[j] = __float2half_rn(v);
    }
    if (idx < XQUADS) {                          // x -> fp16 (per float4)
        float4 v = *(const float4*)&x[(size_t)idx * 4];
        uint2 o;
        o.x = pack_h2(v.x, v.y);
        o.y = pack_h2(v.z, v.w);
        *(uint2*)&g_x16[(size_t)idx * 4] = o;
    }
}

// ==================== CSR build ====================
__device__ __forceinline__ int load_idx(const void* ei, size_t pos) {
    if (g_is64) return (int)((const long long*)ei)[pos];
    return ((const int*)ei)[pos];
}
__global__ void hist_kernel(const void* __restrict__ ei, int E) {
    int e = blockIdx.x * blockDim.x + threadIdx.x;
    if (e < E) {
        int d = load_idx(ei, (size_t)E + e);
        if ((unsigned)d < (unsigned)N_NODES) atomicAdd(&g_deg[d], 1);
    }
}
__global__ void scan_part_kernel() {
    __shared__ int s_woff[32];
    int tid = threadIdx.x, lane = tid & 31, wid = tid >> 5;
    int i = blockIdx.x * 1024 + tid;
    int v = (i < N_NODES) ? g_deg[i] : 0;
    int inc = v;
#pragma unroll
    for (int o = 1; o < 32; o <<= 1) {
        int t = __shfl_up_sync(0xffffffffu, inc, o);
        if (lane >= o) inc += t;
    }
    if (lane == 31) s_woff[wid] = inc;
    __syncthreads();
    if (wid == 0) {
        int ws = s_woff[lane];
        int wi = ws;
#pragma unroll
        for (int o = 1; o < 32; o <<= 1) {
            int t = __shfl_up_sync(0xffffffffu, wi, o);
            if (lane >= o) wi += t;
        }
        s_woff[lane] = wi - ws;
    }
    __syncthreads();
    int excl = s_woff[wid] + inc - v;
    if (i < N_NODES) g_offs[i] = excl;
    if (tid == 1023) g_part[blockIdx.x] = excl + v;
}
__global__ void scan_add_kernel() {     // each block self-computes its prefix over 98 partials
    __shared__ int redA[32], redB[32];
    __shared__ int s_off, s_tot;
    int tid = threadIdx.x, lane = tid & 31, wid = tid >> 5;
    int p  = (tid < NPART) ? g_part[tid] : 0;
    int v1 = (tid < (int)blockIdx.x) ? p : 0;
    int v2 = p;
#pragma unroll
    for (int o = 16; o > 0; o >>= 1) {
        v1 += __shfl_xor_sync(0xffffffffu, v1, o);
        v2 += __shfl_xor_sync(0xffffffffu, v2, o);
    }
    if (lane == 0) { redA[wid] = v1; redB[wid] = v2; }
    __syncthreads();
    if (wid == 0) {
        int a = redA[lane], b = redB[lane];
#pragma unroll
        for (int o = 16; o > 0; o >>= 1) {
            a += __shfl_xor_sync(0xffffffffu, a, o);
            b += __shfl_xor_sync(0xffffffffu, b, o);
        }
        if (lane == 0) { s_off = a; s_tot = b; }
    }
    __syncthreads();
    int i = blockIdx.x * 1024 + tid;
    if (i < N_NODES) {
        int o = g_offs[i] + s_off;
        g_offs[i] = o;
        g_cursor[i] = o;
    }
    if (blockIdx.x == NPART - 1 && tid == 0) g_offs[N_NODES] = s_tot;
}
__global__ void scatter_kernel(const void* __restrict__ ei, int E) {
    int e = blockIdx.x * blockDim.x + threadIdx.x;
    if (e < E) {
        int d = load_idx(ei, (size_t)E + e);
        int s = load_idx(ei, (size_t)e);
        if ((unsigned)d < (unsigned)N_NODES && (unsigned)s < (unsigned)N_NODES) {
            int p = atomicAdd(&g_cursor[d], 1);
            g_src_sorted[p] = s;
        }
    }
}

// ==================== group-parallel aggregation, unroll-4 pipelined ============
// agg1: warp = 4 groups x 8 lanes; 4 independent gathers in flight per group.
__global__ void agg1_kernel() {
    int w = (blockIdx.x * blockDim.x + threadIdx.x) >> 5;
    if (w >= N_NODES) return;
    int lane = threadIdx.x & 31;
    int grp = lane >> 3, gl = lane & 7;
    int beg = g_offs[w], end = g_offs[w + 1];
    float inv = 1.0f / (float)max(end - beg, 1);
    float a[8] = {0.f, 0.f, 0.f, 0.f, 0.f, 0.f, 0.f, 0.f};
    int e = beg + grp;
    for (; e + 12 < end; e += 16) {
        int s0 = g_src_sorted[e];
        int s1 = g_src_sorted[e + 4];
        int s2 = g_src_sorted[e + 8];
        int s3 = g_src_sorted[e + 12];
        uint4 p0 = *(const uint4*)&g_x16[(size_t)s0 * 64 + gl * 8];
        uint4 p1 = *(const uint4*)&g_x16[(size_t)s1 * 64 + gl * 8];
        uint4 p2 = *(const uint4*)&g_x16[(size_t)s2 * 64 + gl * 8];
        uint4 p3 = *(const uint4*)&g_x16[(size_t)s3 * 64 + gl * 8];
        acc8(p0, a); acc8(p1, a); acc8(p2, a); acc8(p3, a);
    }
    for (; e < end; e += 4) {
        int ss = g_src_sorted[e];
        uint4 p = *(const uint4*)&g_x16[(size_t)ss * 64 + gl * 8];
        acc8(p, a);
    }
#pragma unroll
    for (int f = 0; f < 8; f++) {
        a[f] += __shfl_xor_sync(0xffffffffu, a[f], 8);
        a[f] += __shfl_xor_sync(0xffffffffu, a[f], 16);
    }
    if (lane < 8) {
        uint4 o;
        o.x = pack_h2(a[0] * inv, a[1] * inv);
        o.y = pack_h2(a[2] * inv, a[3] * inv);
        o.z = pack_h2(a[4] * inv, a[5] * inv);
        o.w = pack_h2(a[6] * inv, a[7] * inv);
        *(uint4*)&g_A1[(size_t)w * 128 + lane * 8] = o;
    }
    // self part (cols 64..127): straight fp16 copy, all 32 lanes (4B each)
    *(uint32_t*)&g_A1[(size_t)w * 128 + 64 + lane * 2] =
        *(const uint32_t*)&g_x16[(size_t)w * 64 + lane * 2];
}
// agg2: warp = 2 groups x 16 lanes; 4 independent gathers in flight per group.
__global__ void agg2_kernel() {
    int w = (blockIdx.x * blockDim.x + threadIdx.x) >> 5;
    if (w >= N_NODES) return;
    int lane = threadIdx.x & 31;
    int grp = lane >> 4, gl = lane & 15;
    int beg = g_offs[w], end = g_offs[w + 1];
    float inv = 1.0f / (float)max(end - beg, 1);
    float a[8] = {0.f, 0.f, 0.f, 0.f, 0.f, 0.f, 0.f, 0.f};
    int e = beg + grp;
    for (; e + 6 < end; e += 8) {
        int s0 = g_src_sorted[e];
        int s1 = g_src_sorted[e + 2];
        int s2 = g_src_sorted[e + 4];
        int s3 = g_src_sorted[e + 6];
        uint4 p0 = *(const uint4*)&g_A2[(size_t)s0 * 256 + 128 + gl * 8];
        uint4 p1 = *(const uint4*)&g_A2[(size_t)s1 * 256 + 128 + gl * 8];
        uint4 p2 = *(const uint4*)&g_A2[(size_t)s2 * 256 + 128 + gl * 8];
        uint4 p3 = *(const uint4*)&g_A2[(size_t)s3 * 256 + 128 + gl * 8];
        acc8(p0, a); acc8(p1, a); acc8(p2, a); acc8(p3, a);
    }
    for (; e < end; e += 2) {
        int ss = g_src_sorted[e];
        uint4 p = *(const uint4*)&g_A2[(size_t)ss * 256 + 128 + gl * 8];
        acc8(p, a);
    }
#pragma unroll
    for (int f = 0; f < 8; f++)
        a[f] += __shfl_xor_sync(0xffffffffu, a[f], 16);
    if (lane < 16) {
        uint4 o;
        o.x = pack_h2(a[0] * inv, a[1] * inv);
        o.y = pack_h2(a[2] * inv, a[3] * inv);
        o.z = pack_h2(a[4] * inv, a[5] * inv);
        o.w = pack_h2(a[6] * inv, a[7] * inv);
        *(uint4*)&g_A2[(size_t)w * 256 + lane * 8] = o;
    }
}

// ==================== cp.async pipelined fp16 mma GEMM (BK=32) ====================
// CTA 128x128, BK=32 halves, 2-stage double buffer, RS=40 halves (80B rows —
// validated conflict-free layout). 8 warps, warp tile m32 x n64.
template <int KT, bool RELU, int LAYER>
__global__ __launch_bounds__(256) void gemm_fp16_kernel(
    const float* __restrict__ bias, float* __restrict__ out_ext)
{
    constexpr int NCH = KT / 32;
    constexpr int RS = 40;
    constexpr uint32_t ARR_B = 128 * RS * 2;      // 10240 B per array
    constexpr uint32_t STG_B = 2 * ARR_B;         // A + W per stage
    __shared__ __align__(16) __half sbuf[2][2][128 * RS];   // 40 KB

    const __half* A = (LAYER == 1) ? g_A1 : g_A2;
    const __half* W = (LAYER == 1) ? g_w1 : g_w2;

    const int tid = threadIdx.x, lane = tid & 31, wid = tid >> 5;
    const int row0 = blockIdx.x * 128;
    const int valid = min(128, N_NODES - row0);
    const int wr = wid & 3, wc = wid >> 2;

    float c[2][8][4];
#pragma unroll
    for (int mi = 0; mi < 2; mi++)
#pragma unroll
        for (int ni = 0; ni < 8; ni++)
#pragma unroll
            for (int q = 0; q < 4; q++) c[mi][ni][q] = 0.f;

    const uint32_t sb0 = smem_u32(sbuf);

    const int ld_r = tid >> 1;
    const int ld_u = (tid & 1) * 2;
    const int ar = min(row0 + ld_r, N_NODES - 1);
    const size_t goA = (size_t)ar * KT + ld_u * 8;
    const size_t goW = (size_t)ld_r * KT + ld_u * 8;
    const uint32_t dst_ru = (uint32_t)(ld_r * RS + ld_u * 8) * 2;

    const int a_m = ((lane >> 3) & 1) * 8 + (lane & 7);
    const int a_u = (lane >> 4);
    const int b_n = ((lane >> 4) << 3) + (lane & 7);
    const int b_u = ((lane >> 3) & 1);

    {
        uint32_t d = sb0 + dst_ru;
        cp16(d, &A[goA]);            cp16(d + 16, &A[goA + 8]);
        cp16(d + ARR_B, &W[goW]);    cp16(d + ARR_B + 16, &W[goW + 8]);
        CP_COMMIT();
    }

    for (int kc = 0; kc < NCH; kc++) {
        if (kc + 1 < NCH) {
            uint32_t d = sb0 + ((kc + 1) & 1) * STG_B + dst_ru;
            size_t ko = (size_t)(kc + 1) * 32;
            cp16(d, &A[goA + ko]);            cp16(d + 16, &A[goA + ko + 8]);
            cp16(d + ARR_B, &W[goW + ko]);    cp16(d + ARR_B + 16, &W[goW + ko + 8]);
            CP_COMMIT();
            CP_WAIT1();
        } else {
            CP_WAIT0();
        }
        __syncthreads();

        const uint32_t sa = sb0 + (kc & 1) * STG_B;
        const uint32_t sw = sa + ARR_B;

#pragma unroll
        for (int ks = 0; ks < 2; ks++) {
            uint32_t af[2][4], bf[8][2];
#pragma unroll
            for (int mi = 0; mi < 2; mi++) {
                int rr = wr * 32 + mi * 16 + a_m;
                uint32_t off = (uint32_t)(rr * RS + (ks * 2 + a_u) * 8) * 2;
                LDSM_X4(af[mi][0], af[mi][1], af[mi][2], af[mi][3], sa + off);
            }
#pragma unroll
            for (int nj = 0; nj < 4; nj++) {
                int nr = wc * 64 + nj * 16 + b_n;
                uint32_t off = (uint32_t)(nr * RS + (ks * 2 + b_u) * 8) * 2;
                LDSM_X4(bf[nj * 2][0], bf[nj * 2][1], bf[nj * 2 + 1][0], bf[nj * 2 + 1][1], sw + off);
            }
#pragma unroll
            for (int mi = 0; mi < 2; mi++)
#pragma unroll
                for (int ni = 0; ni < 8; ni++)
                    MMA16816F(c[mi][ni], af[mi], bf[ni]);
        }
        __syncthreads();
    }

    // ---- epilogue: bias + (relu); layer1 -> h (fp16) into A2 cols 128..255 ----
    const int g = lane >> 2, tg = lane & 3;
#pragma unroll
    for (int ni = 0; ni < 8; ni++) {
        int col = wc * 64 + ni * 8 + tg * 2;
        float2 bv = *(const float2*)&bias[col];
#pragma unroll
        for (int mi = 0; mi < 2; mi++) {
            int rl = wr * 32 + mi * 16 + g;
#pragma unroll
            for (int hrow = 0; hrow < 2; hrow++) {
                int r = rl + hrow * 8;
                if (r >= valid) continue;
                float v0 = c[mi][ni][hrow * 2 + 0] + bv.x;
                float v1 = c[mi][ni][hrow * 2 + 1] + bv.y;
                if (RELU) { v0 = fmaxf(v0, 0.f); v1 = fmaxf(v1, 0.f); }
                size_t grow = (size_t)(row0 + r);
                if (LAYER == 1) {
                    *(uint32_t*)&g_A2[grow * 256 + 128 + col] = pack_h2(v0, v1);
                } else {
                    float2 o; o.x = v0; o.y = v1;
                    *(float2*)&out_ext[grow * 128 + col] = o;
                }
            }
        }
    }
}

// ==================== entry point ====================
extern "C" void kernel_launch(void* const* d_in, const int* in_sizes, int n_in,
                              void* d_out, int out_size)
{
    (void)n_in; (void)out_size;
    const float* x   = (const float*)d_in[0];
    const void*  ei  = d_in[1];
    const float* W1l = (const float*)d_in[2];
    const float* W1r = (const float*)d_in[3];
    const float* b1  = (const float*)d_in[4];
    const float* W2l = (const float*)d_in[5];
    const float* W2r = (const float*)d_in[6];
    const float* b2  = (const float*)d_in[7];
    float*       out = (float*)d_out;

    int E = in_sizes[1] / 2;
    if (E > E_MAX) E = E_MAX;

    const int agg_blocks  = (N_NODES * 32 + 255) / 256;   // warp per node
    const int gemm_blocks = (N_NODES + 127) / 128;        // 782

    init_kernel<<<(XQUADS + 255) / 256, 256>>>((const int*)ei, in_sizes[1], x,
                                               W1l, W1r, W2l, W2r);        // 0
    hist_kernel<<<(E + 255) / 256, 256>>>(ei, E);                           // 1
    scan_part_kernel<<<NPART, 1024>>>();                                    // 2
    scan_add_kernel<<<NPART, 1024>>>();                                     // 3
    scatter_kernel<<<(E + 255) / 256, 256>>>(ei, E);                        // 4
    agg1_kernel<<<agg_blocks, 256>>>();                                     // 5
    gemm_fp16_kernel<128, true, 1><<<gemm_blocks, 256>>>(b1, nullptr);      // 6
    agg2_kernel<<<agg_blocks, 256>>>();                                     // 7
    gemm_fp16_kernel<256, false, 2><<<gemm_blocks, 256>>>(b2, out);         // 8
}

// round 12
// speedup vs baseline: 1.8367x; 1.1005x over previous
#include <cuda_runtime.h>
#include <cuda_fp16.h>
#include <cstdint>

#define N_NODES 100000
#define E_MAX   1600000
#define NPART   98          // ceil(100000/1024)
#define XQUADS  (N_NODES * 16)   // x as float4: 100000*64/4 = 1.6M

// ---------------- device scratch (static; zero-init, no dynamic allocation) -----
__device__ int    g_is64;
__device__ int    g_deg[N_NODES];        // zeroed by scatter (prev call) / static
__device__ int    g_offs[N_NODES + 1];
__device__ int    g_cursor[N_NODES];
__device__ int    g_blk_total[NPART];
__device__ int    g_blk_flag[NPART];     // zeroed by scatter (prev call) / static
__device__ int    g_src_sorted[E_MAX];
__device__ __half g_x16[(size_t)N_NODES * 64];    // fp16 copy of x
// fp16 operands:  A1 = [agg1 | x] (stride 128),  A2 = [agg2 | h] (stride 256)
__device__ __half g_A1[(size_t)N_NODES * 128];
__device__ __half g_A2[(size_t)N_NODES * 256];
__device__ __half g_w1[128 * 128];    // [n][k] concat(W1l, W1r)
__device__ __half g_w2[128 * 256];    // [n][k] concat(W2l, W2r)

// ==================== PTX helpers (family-portable) ====================
__device__ __forceinline__ uint32_t smem_u32(const void* p) {
    uint32_t a;
    asm("{ .reg .u64 t; cvta.to.shared.u64 t, %1; cvt.u32.u64 %0, t; }" : "=r"(a) : "l"(p));
    return a;
}
#define LDSM_X4(r0, r1, r2, r3, addr)                                           \
    asm volatile("ldmatrix.sync.aligned.m8n8.x4.shared.b16 {%0,%1,%2,%3}, [%4];" \
                 : "=r"(r0), "=r"(r1), "=r"(r2), "=r"(r3) : "r"(addr))
#define MMA16816F(c, a, b)                                                       \
    asm volatile("mma.sync.aligned.m16n8k16.row.col.f32.f16.f16.f32 "            \
                 "{%0,%1,%2,%3}, {%4,%5,%6,%7}, {%8,%9}, {%0,%1,%2,%3};"         \
                 : "+f"((c)[0]), "+f"((c)[1]), "+f"((c)[2]), "+f"((c)[3])        \
                 : "r"((a)[0]), "r"((a)[1]), "r"((a)[2]), "r"((a)[3]),           \
                   "r"((b)[0]), "r"((b)[1]))
__device__ __forceinline__ void cp16(uint32_t dst, const void* src) {
    asm volatile("cp.async.cg.shared.global [%0], [%1], 16;" :: "r"(dst), "l"(src));
}
#define CP_COMMIT() asm volatile("cp.async.commit_group;" ::: "memory")
#define CP_WAIT1()  asm volatile("cp.async.wait_group 1;" ::: "memory")
#define CP_WAIT0()  asm volatile("cp.async.wait_group 0;" ::: "memory")

__device__ __forceinline__ uint32_t pack_h2(float a, float b) {
    __half2 h = __floats2half2_rn(a, b);
    return *(uint32_t*)&h;
}
// accumulate 8 halves (uint4) into 8 fp32 accumulators
__device__ __forceinline__ void acc8(const uint4& p, float* a) {
    float2 f0 = __half22float2(*(const __half2*)&p.x);
    float2 f1 = __half22float2(*(const __half2*)&p.y);
    float2 f2 = __half22float2(*(const __half2*)&p.z);
    float2 f3 = __half22float2(*(const __half2*)&p.w);
    a[0] += f0.x; a[1] += f0.y; a[2] += f1.x; a[3] += f1.y;
    a[4] += f2.x; a[5] += f2.y; a[6] += f3.x; a[7] += f3.y;
}

// ==================== launch 0: init (detect + weights + x->fp16 + HIST) ========
// g_deg arrives zeroed (static init on first call; scatter re-zeroes for next).
__global__ void init_kernel(const void* __restrict__ ei, const int* __restrict__ ei32,
                            int n_words, int E,
                            const float* __restrict__ x,
                            const float* __restrict__ W1l, const float* __restrict__ W1r,
                            const float* __restrict__ W2l, const float* __restrict__ W2r) {
    __shared__ int s_is64;
    int idx = blockIdx.x * blockDim.x + threadIdx.x;
    // per-block dtype detection (redundant but removes cross-kernel dependency)
    if (threadIdx.x < 32) {
        int lane = threadIdx.x;
        int wi = 1 + 2 * lane;
        int z = (wi < n_words && ei32[wi] == 0) ? 1 : 0;
        unsigned m = __ballot_sync(0xffffffffu, z);
        if (lane == 0) {
            s_is64 = (__popc(m) > 24) ? 1 : 0;
            if (blockIdx.x == 0) g_is64 = s_is64;
        }
    }
    __syncthreads();
    int is64 = s_is64;
    // histogram of dst
    if (idx < E) {
        int d = is64 ? (int)((const long long*)ei)[(size_t)E + idx]
                     : ((const int*)ei)[(size_t)E + idx];
        if ((unsigned)d < (unsigned)N_NODES) atomicAdd(&g_deg[d], 1);
    }
    if (idx < 128 * 128) {                       // layer 1 weights: Ktot=128, Kh=64
        int n = idx >> 7, k = idx & 127;
        float v = (k < 64) ? W1l[n * 64 + k] : W1r[n * 64 + (k - 64)];
        g_w1[idx] = __float2half_rn(v);
    } else if (idx < 128 * 128 + 128 * 256) {    // layer 2 weights: Ktot=256, Kh=128
        int j = idx - 128 * 128;
        int n = j >> 8, k = j & 255;
        float v = (k < 128) ? W2l[n * 128 + k] : W2r[n * 128 + (k - 128)];
        g_w2[j] = __float2half_rn(v);
    }
    if (idx < XQUADS) {                          // x -> fp16 (per float4)
        float4 v = *(const float4*)&x[(size_t)idx * 4];
        uint2 o;
        o.x = pack_h2(v.x, v.y);
        o.y = pack_h2(v.z, v.w);
        *(uint2*)&g_x16[(size_t)idx * 4] = o;
    }
}

// ==================== launch 1: single-pass scan (decoupled lookback) ===========
// 98 blocks x 1024 threads, all co-resident (98 < 148 SMs / 2 blocks per SM).
__global__ void scan_kernel() {
    __shared__ int s_woff[32];
    __shared__ int s_red[4];
    __shared__ int s_pred;
    int tid = threadIdx.x, lane = tid & 31, wid = tid >> 5;
    int bid = blockIdx.x;
    int i = bid * 1024 + tid;
    int v = (i < N_NODES) ? g_deg[i] : 0;
    int inc = v;
#pragma unroll
    for (int o = 1; o < 32; o <<= 1) {
        int t = __shfl_up_sync(0xffffffffu, inc, o);
        if (lane >= o) inc += t;
    }
    if (lane == 31) s_woff[wid] = inc;
    __syncthreads();
    if (wid == 0) {
        int ws = s_woff[lane];
        int wi = ws;
#pragma unroll
        for (int o = 1; o < 32; o <<= 1) {
            int t = __shfl_up_sync(0xffffffffu, wi, o);
            if (lane >= o) wi += t;
        }
        s_woff[lane] = wi - ws;
    }
    __syncthreads();
    int excl = s_woff[wid] + inc - v;
    // publish this block's total
    if (tid == 1023) {
        g_blk_total[bid] = excl + v;
        __threadfence();
        atomicExch(&g_blk_flag[bid], 1);
    }
    // gather predecessor totals (threads 0..bid-1 each poll one block)
    int myp = 0;
    if (tid < bid) {
        while (atomicAdd(&g_blk_flag[tid], 0) == 0) {}
        myp = atomicAdd(&g_blk_total[tid], 0);
    }
    if (tid < 128) {
#pragma unroll
        for (int o = 16; o > 0; o >>= 1)
            myp += __shfl_xor_sync(0xffffffffu, myp, o);
        if (lane == 0) s_red[wid] = myp;
    }
    __syncthreads();
    if (tid == 0) s_pred = s_red[0] + s_red[1] + s_red[2] + s_red[3];
    __syncthreads();
    int off = s_pred;
    if (i < N_NODES) {
        int o = excl + off;
        g_offs[i] = o;
        g_cursor[i] = o;
    }
    if (bid == NPART - 1 && tid == 1023) g_offs[N_NODES] = off + excl + v;
}

// ==================== launch 2: scatter (+ cleanup for next call) ===============
__global__ void scatter_kernel(const void* __restrict__ ei, int E) {
    int e = blockIdx.x * blockDim.x + threadIdx.x;
    int is64 = g_is64;
    if (e < E) {
        int d, s;
        if (is64) {
            d = (int)((const long long*)ei)[(size_t)E + e];
            s = (int)((const long long*)ei)[(size_t)e];
        } else {
            d = ((const int*)ei)[(size_t)E + e];
            s = ((const int*)ei)[(size_t)e];
        }
        if ((unsigned)d < (unsigned)N_NODES && (unsigned)s < (unsigned)N_NODES) {
            int p = atomicAdd(&g_cursor[d], 1);
            g_src_sorted[p] = s;
        }
    }
    // cleanup for the NEXT kernel_launch call (g_deg consumed by scan already)
    if (e < N_NODES) g_deg[e] = 0;
    if (e < NPART) g_blk_flag[e] = 0;
}

// ==================== aggregation: node-per-group ====================
// agg1: warp = 4 nodes; group of 8 lanes owns one node (lane's 16B = 8 features).
__global__ void agg1_kernel() {
    int gt = blockIdx.x * blockDim.x + threadIdx.x;
    int warp = gt >> 5, lane = threadIdx.x & 31;
    int grp = lane >> 3, gl = lane & 7;
    int w = warp * 4 + grp;
    if (w >= N_NODES) return;
    int beg = g_offs[w], end = g_offs[w + 1];
    float inv = 1.0f / (float)max(end - beg, 1);
    float a[8] = {0.f, 0.f, 0.f, 0.f, 0.f, 0.f, 0.f, 0.f};
    int e = beg;
    for (; e + 3 < end; e += 4) {
        int s0 = g_src_sorted[e];
        int s1 = g_src_sorted[e + 1];
        int s2 = g_src_sorted[e + 2];
        int s3 = g_src_sorted[e + 3];
        uint4 p0 = *(const uint4*)&g_x16[(size_t)s0 * 64 + gl * 8];
        uint4 p1 = *(const uint4*)&g_x16[(size_t)s1 * 64 + gl * 8];
        uint4 p2 = *(const uint4*)&g_x16[(size_t)s2 * 64 + gl * 8];
        uint4 p3 = *(const uint4*)&g_x16[(size_t)s3 * 64 + gl * 8];
        acc8(p0, a); acc8(p1, a); acc8(p2, a); acc8(p3, a);
    }
    for (; e < end; e++) {
        int ss = g_src_sorted[e];
        uint4 p = *(const uint4*)&g_x16[(size_t)ss * 64 + gl * 8];
        acc8(p, a);
    }
    uint4 o;
    o.x = pack_h2(a[0] * inv, a[1] * inv);
    o.y = pack_h2(a[2] * inv, a[3] * inv);
    o.z = pack_h2(a[4] * inv, a[5] * inv);
    o.w = pack_h2(a[6] * inv, a[7] * inv);
    *(uint4*)&g_A1[(size_t)w * 128 + gl * 8] = o;
    // self part (cols 64..127): straight fp16 copy, 8 lanes x 16B = full row
    *(uint4*)&g_A1[(size_t)w * 128 + 64 + gl * 8] =
        *(const uint4*)&g_x16[(size_t)w * 64 + gl * 8];
}
// agg2: warp = 2 nodes; group of 16 lanes owns one node (lane's 16B over 256B row).
__global__ void agg2_kernel() {
    int gt = blockIdx.x * blockDim.x + threadIdx.x;
    int warp = gt >> 5, lane = threadIdx.x & 31;
    int grp = lane >> 4, gl = lane & 15;
    int w = warp * 2 + grp;
    if (w >= N_NODES) return;
    int beg = g_offs[w], end = g_offs[w + 1];
    float inv = 1.0f / (float)max(end - beg, 1);
    float a[8] = {0.f, 0.f, 0.f, 0.f, 0.f, 0.f, 0.f, 0.f};
    int e = beg;
    for (; e + 3 < end; e += 4) {
        int s0 = g_src_sorted[e];
        int s1 = g_src_sorted[e + 1];
        int s2 = g_src_sorted[e + 2];
        int s3 = g_src_sorted[e + 3];
        uint4 p0 = *(const uint4*)&g_A2[(size_t)s0 * 256 + 128 + gl * 8];
        uint4 p1 = *(const uint4*)&g_A2[(size_t)s1 * 256 + 128 + gl * 8];
        uint4 p2 = *(const uint4*)&g_A2[(size_t)s2 * 256 + 128 + gl * 8];
        uint4 p3 = *(const uint4*)&g_A2[(size_t)s3 * 256 + 128 + gl * 8];
        acc8(p0, a); acc8(p1, a); acc8(p2, a); acc8(p3, a);
    }
    for (; e < end; e++) {
        int ss = g_src_sorted[e];
        uint4 p = *(const uint4*)&g_A2[(size_t)ss * 256 + 128 + gl * 8];
        acc8(p, a);
    }
    uint4 o;
    o.x = pack_h2(a[0] * inv, a[1] * inv);
    o.y = pack_h2(a[2] * inv, a[3] * inv);
    o.z = pack_h2(a[4] * inv, a[5] * inv);
    o.w = pack_h2(a[6] * inv, a[7] * inv);
    *(uint4*)&g_A2[(size_t)w * 256 + gl * 8] = o;
}

// ==================== cp.async pipelined fp16 mma GEMM (BK=32) ====================
// CTA 128x128, BK=32 halves, 2-stage double buffer, RS=40 halves (80B rows —
// validated conflict-free layout). 8 warps, warp tile m32 x n64.
template <int KT, bool RELU, int LAYER>
__global__ __launch_bounds__(256) void gemm_fp16_kernel(
    const float* __restrict__ bias, float* __restrict__ out_ext)
{
    constexpr int NCH = KT / 32;
    constexpr int RS = 40;
    constexpr uint32_t ARR_B = 128 * RS * 2;      // 10240 B per array
    constexpr uint32_t STG_B = 2 * ARR_B;         // A + W per stage
    __shared__ __align__(16) __half sbuf[2][2][128 * RS];   // 40 KB

    const __half* A = (LAYER == 1) ? g_A1 : g_A2;
    const __half* W = (LAYER == 1) ? g_w1 : g_w2;

    const int tid = threadIdx.x, lane = tid & 31, wid = tid >> 5;
    const int row0 = blockIdx.x * 128;
    const int valid = min(128, N_NODES - row0);
    const int wr = wid & 3, wc = wid >> 2;

    float c[2][8][4];
#pragma unroll
    for (int mi = 0; mi < 2; mi++)
#pragma unroll
        for (int ni = 0; ni < 8; ni++)
#pragma unroll
            for (int q = 0; q < 4; q++) c[mi][ni][q] = 0.f;

    const uint32_t sb0 = smem_u32(sbuf);

    const int ld_r = tid >> 1;
    const int ld_u = (tid & 1) * 2;
    const int ar = min(row0 + ld_r, N_NODES - 1);
    const size_t goA = (size_t)ar * KT + ld_u * 8;
    const size_t goW = (size_t)ld_r * KT + ld_u * 8;
    const uint32_t dst_ru = (uint32_t)(ld_r * RS + ld_u * 8) * 2;

    const int a_m = ((lane >> 3) & 1) * 8 + (lane & 7);
    const int a_u = (lane >> 4);
    const int b_n = ((lane >> 4) << 3) + (lane & 7);
    const int b_u = ((lane >> 3) & 1);

    {
        uint32_t d = sb0 + dst_ru;
        cp16(d, &A[goA]);            cp16(d + 16, &A[goA + 8]);
        cp16(d + ARR_B, &W[goW]);    cp16(d + ARR_B + 16, &W[goW + 8]);
        CP_COMMIT();
    }

    for (int kc = 0; kc < NCH; kc++) {
        if (kc + 1 < NCH) {
            uint32_t d = sb0 + ((kc + 1) & 1) * STG_B + dst_ru;
            size_t ko = (size_t)(kc + 1) * 32;
            cp16(d, &A[goA + ko]);            cp16(d + 16, &A[goA + ko + 8]);
            cp16(d + ARR_B, &W[goW + ko]);    cp16(d + ARR_B + 16, &W[goW + ko + 8]);
            CP_COMMIT();
            CP_WAIT1();
        } else {
            CP_WAIT0();
        }
        __syncthreads();

        const uint32_t sa = sb0 + (kc & 1) * STG_B;
        const uint32_t sw = sa + ARR_B;

#pragma unroll
        for (int ks = 0; ks < 2; ks++) {
            uint32_t af[2][4], bf[8][2];
#pragma unroll
            for (int mi = 0; mi < 2; mi++) {
                int rr = wr * 32 + mi * 16 + a_m;
                uint32_t off = (uint32_t)(rr * RS + (ks * 2 + a_u) * 8) * 2;
                LDSM_X4(af[mi][0], af[mi][1], af[mi][2], af[mi][3], sa + off);
            }
#pragma unroll
            for (int nj = 0; nj < 4; nj++) {
                int nr = wc * 64 + nj * 16 + b_n;
                uint32_t off = (uint32_t)(nr * RS + (ks * 2 + b_u) * 8) * 2;
                LDSM_X4(bf[nj * 2][0], bf[nj * 2][1], bf[nj * 2 + 1][0], bf[nj * 2 + 1][1], sw + off);
            }
#pragma unroll
            for (int mi = 0; mi < 2; mi++)
#pragma unroll
                for (int ni = 0; ni < 8; ni++)
                    MMA16816F(c[mi][ni], af[mi], bf[ni]);
        }
        __syncthreads();
    }

    // ---- epilogue: bias + (relu); layer1 -> h (fp16) into A2 cols 128..255 ----
    const int g = lane >> 2, tg = lane & 3;
#pragma unroll
    for (int ni = 0; ni < 8; ni++) {
        int col = wc * 64 + ni * 8 + tg * 2;
        float2 bv = *(const float2*)&bias[col];
#pragma unroll
        for (int mi = 0; mi < 2; mi++) {
            int rl = wr * 32 + mi * 16 + g;
#pragma unroll
            for (int hrow = 0; hrow < 2; hrow++) {
                int r = rl + hrow * 8;
                if (r >= valid) continue;
                float v0 = c[mi][ni][hrow * 2 + 0] + bv.x;
                float v1 = c[mi][ni][hrow * 2 + 1] + bv.y;
                if (RELU) { v0 = fmaxf(v0, 0.f); v1 = fmaxf(v1, 0.f); }
                size_t grow = (size_t)(row0 + r);
                if (LAYER == 1) {
                    *(uint32_t*)&g_A2[grow * 256 + 128 + col] = pack_h2(v0, v1);
                } else {
                    float2 o; o.x = v0; o.y = v1;
                    *(float2*)&out_ext[grow * 128 + col] = o;
                }
            }
        }
    }
}

// ==================== entry point ====================
extern "C" void kernel_launch(void* const* d_in, const int* in_sizes, int n_in,
                              void* d_out, int out_size)
{
    (void)n_in; (void)out_size;
    const float* x   = (const float*)d_in[0];
    const void*  ei  = d_in[1];
    const float* W1l = (const float*)d_in[2];
    const float* W1r = (const float*)d_in[3];
    const float* b1  = (const float*)d_in[4];
    const float* W2l = (const float*)d_in[5];
    const float* W2r = (const float*)d_in[6];
    const float* b2  = (const float*)d_in[7];
    float*       out = (float*)d_out;

    int E = in_sizes[1] / 2;
    if (E > E_MAX) E = E_MAX;

    const int agg1_blocks = (((N_NODES + 3) / 4) * 32 + 255) / 256;   // 3125
    const int agg2_blocks = (((N_NODES + 1) / 2) * 32 + 255) / 256;   // 6250
    const int gemm_blocks = (N_NODES + 127) / 128;                    // 782

    init_kernel<<<(E + 255) / 256, 256>>>(ei, (const int*)ei, in_sizes[1], E, x,
                                          W1l, W1r, W2l, W2r);         // 0
    scan_kernel<<<NPART, 1024>>>();                                     // 1
    scatter_kernel<<<(E + 255) / 256, 256>>>(ei, E);                    // 2
    agg1_kernel<<<agg1_blocks, 256>>>();                                // 3 <- profiled
    gemm_fp16_kernel<128, true, 1><<<gemm_blocks, 256>>>(b1, nullptr);  // 4
    agg2_kernel<<<agg2_blocks, 256>>>();                                // 5
    gemm_fp16_kernel<256, false, 2><<<gemm_blocks, 256>>>(b2, out);     // 6
}

// round 13
// speedup vs baseline: 1.9126x; 1.0413x over previous
#include <cuda_runtime.h>
#include <cuda_fp16.h>
#include <cstdint>

#define N_NODES 100000
#define E_MAX   1600000
#define NPART   98          // ceil(100000/1024)
#define XQUADS  (N_NODES * 16)   // x as float4: 100000*64/4 = 1.6M

// ---------------- device scratch (static; zero-init, no dynamic allocation) -----
__device__ int    g_is64;
__device__ int    g_deg[N_NODES];        // zeroed by scatter (prev call) / static
__device__ int    g_offs[N_NODES + 1];
__device__ int    g_cursor[N_NODES];
__device__ int    g_blk_total[NPART];
__device__ int    g_blk_flag[NPART];     // zeroed by scatter (prev call) / static
__device__ int    g_src_sorted[E_MAX];
__device__ __half g_x16[(size_t)N_NODES * 64];    // fp16 copy of x
// fp16 operands:  A1 = [agg1 | x] (stride 128),  A2 = [agg2 | h] (stride 256)
__device__ __half g_A1[(size_t)N_NODES * 128];
__device__ __half g_A2[(size_t)N_NODES * 256];
__device__ __half g_w1[128 * 128];    // [n][k] concat(W1l, W1r)
__device__ __half g_w2[128 * 256];    // [n][k] concat(W2l, W2r)

// ==================== PTX helpers (family-portable) ====================
__device__ __forceinline__ uint32_t smem_u32(const void* p) {
    uint32_t a;
    asm("{ .reg .u64 t; cvta.to.shared.u64 t, %1; cvt.u32.u64 %0, t; }" : "=r"(a) : "l"(p));
    return a;
}
#define LDSM_X4(r0, r1, r2, r3, addr)                                           \
    asm volatile("ldmatrix.sync.aligned.m8n8.x4.shared.b16 {%0,%1,%2,%3}, [%4];" \
                 : "=r"(r0), "=r"(r1), "=r"(r2), "=r"(r3) : "r"(addr))
#define MMA16816F(c, a, b)                                                       \
    asm volatile("mma.sync.aligned.m16n8k16.row.col.f32.f16.f16.f32 "            \
                 "{%0,%1,%2,%3}, {%4,%5,%6,%7}, {%8,%9}, {%0,%1,%2,%3};"         \
                 : "+f"((c)[0]), "+f"((c)[1]), "+f"((c)[2]), "+f"((c)[3])        \
                 : "r"((a)[0]), "r"((a)[1]), "r"((a)[2]), "r"((a)[3]),           \
                   "r"((b)[0]), "r"((b)[1]))
__device__ __forceinline__ void cp16(uint32_t dst, const void* src) {
    asm volatile("cp.async.cg.shared.global [%0], [%1], 16;" :: "r"(dst), "l"(src));
}
#define CP_COMMIT() asm volatile("cp.async.commit_group;" ::: "memory")
#define CP_WAIT1()  asm volatile("cp.async.wait_group 1;" ::: "memory")
#define CP_WAIT0()  asm volatile("cp.async.wait_group 0;" ::: "memory")

__device__ __forceinline__ uint32_t pack_h2(float a, float b) {
    __half2 h = __floats2half2_rn(a, b);
    return *(uint32_t*)&h;
}
__device__ __forceinline__ __half2 u2h(uint32_t u) { return *(__half2*)&u; }
// accumulate 8 halves (uint4) into 8 fp32 accumulators (exact path, remainders)
__device__ __forceinline__ void acc8(const uint4& p, float* a) {
    float2 f0 = __half22float2(u2h(p.x));
    float2 f1 = __half22float2(u2h(p.y));
    float2 f2 = __half22float2(u2h(p.z));
    float2 f3 = __half22float2(u2h(p.w));
    a[0] += f0.x; a[1] += f0.y; a[2] += f1.x; a[3] += f1.y;
    a[4] += f2.x; a[5] += f2.y; a[6] += f3.x; a[7] += f3.y;
}
// fp16 pairwise tree over 4 edges' words, single fp32 flush (7 ops/word vs 16)
__device__ __forceinline__ void acc8_tree4(const uint4& p0, const uint4& p1,
                                           const uint4& p2, const uint4& p3, float* a) {
    __half2 t;
    float2 f;
    t = __hadd2(__hadd2(u2h(p0.x), u2h(p1.x)), __hadd2(u2h(p2.x), u2h(p3.x)));
    f = __half22float2(t); a[0] += f.x; a[1] += f.y;
    t = __hadd2(__hadd2(u2h(p0.y), u2h(p1.y)), __hadd2(u2h(p2.y), u2h(p3.y)));
    f = __half22float2(t); a[2] += f.x; a[3] += f.y;
    t = __hadd2(__hadd2(u2h(p0.z), u2h(p1.z)), __hadd2(u2h(p2.z), u2h(p3.z)));
    f = __half22float2(t); a[4] += f.x; a[5] += f.y;
    t = __hadd2(__hadd2(u2h(p0.w), u2h(p1.w)), __hadd2(u2h(p2.w), u2h(p3.w)));
    f = __half22float2(t); a[6] += f.x; a[7] += f.y;
}

// ==================== launch 0: init (detect + weights + x->fp16 + HIST) ========
__global__ void init_kernel(const void* __restrict__ ei, const int* __restrict__ ei32,
                            int n_words, int E,
                            const float* __restrict__ x,
                            const float* __restrict__ W1l, const float* __restrict__ W1r,
                            const float* __restrict__ W2l, const float* __restrict__ W2r) {
    __shared__ int s_is64;
    int idx = blockIdx.x * blockDim.x + threadIdx.x;
    if (threadIdx.x < 32) {
        int lane = threadIdx.x;
        int wi = 1 + 2 * lane;
        int z = (wi < n_words && ei32[wi] == 0) ? 1 : 0;
        unsigned m = __ballot_sync(0xffffffffu, z);
        if (lane == 0) {
            s_is64 = (__popc(m) > 24) ? 1 : 0;
            if (blockIdx.x == 0) g_is64 = s_is64;
        }
    }
    __syncthreads();
    int is64 = s_is64;
    if (idx < E) {
        int d = is64 ? (int)((const long long*)ei)[(size_t)E + idx]
                     : ((const int*)ei)[(size_t)E + idx];
        if ((unsigned)d < (unsigned)N_NODES) atomicAdd(&g_deg[d], 1);
    }
    if (idx < 128 * 128) {                       // layer 1 weights: Ktot=128, Kh=64
        int n = idx >> 7, k = idx & 127;
        float v = (k < 64) ? W1l[n * 64 + k] : W1r[n * 64 + (k - 64)];
        g_w1[idx] = __float2half_rn(v);
    } else if (idx < 128 * 128 + 128 * 256) {    // layer 2 weights: Ktot=256, Kh=128
        int j = idx - 128 * 128;
        int n = j >> 8, k = j & 255;
        float v = (k < 128) ? W2l[n * 128 + k] : W2r[n * 128 + (k - 128)];
        g_w2[j] = __float2half_rn(v);
    }
    if (idx < XQUADS) {                          // x -> fp16 (per float4)
        float4 v = *(const float4*)&x[(size_t)idx * 4];
        uint2 o;
        o.x = pack_h2(v.x, v.y);
        o.y = pack_h2(v.z, v.w);
        *(uint2*)&g_x16[(size_t)idx * 4] = o;
    }
}

// ==================== launch 1: single-pass scan (decoupled lookback) ===========
__global__ void scan_kernel() {
    __shared__ int s_woff[32];
    __shared__ int s_red[4];
    __shared__ int s_pred;
    int tid = threadIdx.x, lane = tid & 31, wid = tid >> 5;
    int bid = blockIdx.x;
    int i = bid * 1024 + tid;
    int v = (i < N_NODES) ? g_deg[i] : 0;
    int inc = v;
#pragma unroll
    for (int o = 1; o < 32; o <<= 1) {
        int t = __shfl_up_sync(0xffffffffu, inc, o);
        if (lane >= o) inc += t;
    }
    if (lane == 31) s_woff[wid] = inc;
    __syncthreads();
    if (wid == 0) {
        int ws = s_woff[lane];
        int wi = ws;
#pragma unroll
        for (int o = 1; o < 32; o <<= 1) {
            int t = __shfl_up_sync(0xffffffffu, wi, o);
            if (lane >= o) wi += t;
        }
        s_woff[lane] = wi - ws;
    }
    __syncthreads();
    int excl = s_woff[wid] + inc - v;
    if (tid == 1023) {
        g_blk_total[bid] = excl + v;
        __threadfence();
        atomicExch(&g_blk_flag[bid], 1);
    }
    int myp = 0;
    if (tid < bid) {
        while (atomicAdd(&g_blk_flag[tid], 0) == 0) {}
        myp = atomicAdd(&g_blk_total[tid], 0);
    }
    if (tid < 128) {
#pragma unroll
        for (int o = 16; o > 0; o >>= 1)
            myp += __shfl_xor_sync(0xffffffffu, myp, o);
        if (lane == 0) s_red[wid] = myp;
    }
    __syncthreads();
    if (tid == 0) s_pred = s_red[0] + s_red[1] + s_red[2] + s_red[3];
    __syncthreads();
    int off = s_pred;
    if (i < N_NODES) {
        int o = excl + off;
        g_offs[i] = o;
        g_cursor[i] = o;
    }
    if (bid == NPART - 1 && tid == 1023) g_offs[N_NODES] = off + excl + v;
}

// ==================== launch 2: scatter (+ cleanup for next call) ===============
__global__ void scatter_kernel(const void* __restrict__ ei, int E) {
    int e = blockIdx.x * blockDim.x + threadIdx.x;
    int is64 = g_is64;
    if (e < E) {
        int d, s;
        if (is64) {
            d = (int)((const long long*)ei)[(size_t)E + e];
            s = (int)((const long long*)ei)[(size_t)e];
        } else {
            d = ((const int*)ei)[(size_t)E + e];
            s = ((const int*)ei)[(size_t)e];
        }
        if ((unsigned)d < (unsigned)N_NODES && (unsigned)s < (unsigned)N_NODES) {
            int p = atomicAdd(&g_cursor[d], 1);
            g_src_sorted[p] = s;
        }
    }
    if (e < N_NODES) g_deg[e] = 0;
    if (e < NPART) g_blk_flag[e] = 0;
}

// ==================== aggregation: node-per-group, fp16 tree accumulate =========
// agg1: warp = 4 nodes; group of 8 lanes owns one node (lane's 16B = 8 features).
__global__ void agg1_kernel() {
    int gt = blockIdx.x * blockDim.x + threadIdx.x;
    int warp = gt >> 5, lane = threadIdx.x & 31;
    int grp = lane >> 3, gl = lane & 7;
    int w = warp * 4 + grp;
    if (w >= N_NODES) return;
    int beg = g_offs[w], end = g_offs[w + 1];
    float inv = 1.0f / (float)max(end - beg, 1);
    float a[8] = {0.f, 0.f, 0.f, 0.f, 0.f, 0.f, 0.f, 0.f};
    int e = beg;
    for (; e + 3 < end; e += 4) {
        int s0 = g_src_sorted[e];
        int s1 = g_src_sorted[e + 1];
        int s2 = g_src_sorted[e + 2];
        int s3 = g_src_sorted[e + 3];
        uint4 p0 = *(const uint4*)&g_x16[(size_t)s0 * 64 + gl * 8];
        uint4 p1 = *(const uint4*)&g_x16[(size_t)s1 * 64 + gl * 8];
        uint4 p2 = *(const uint4*)&g_x16[(size_t)s2 * 64 + gl * 8];
        uint4 p3 = *(const uint4*)&g_x16[(size_t)s3 * 64 + gl * 8];
        acc8_tree4(p0, p1, p2, p3, a);
    }
    for (; e < end; e++) {
        int ss = g_src_sorted[e];
        uint4 p = *(const uint4*)&g_x16[(size_t)ss * 64 + gl * 8];
        acc8(p, a);
    }
    uint4 o;
    o.x = pack_h2(a[0] * inv, a[1] * inv);
    o.y = pack_h2(a[2] * inv, a[3] * inv);
    o.z = pack_h2(a[4] * inv, a[5] * inv);
    o.w = pack_h2(a[6] * inv, a[7] * inv);
    *(uint4*)&g_A1[(size_t)w * 128 + gl * 8] = o;
    *(uint4*)&g_A1[(size_t)w * 128 + 64 + gl * 8] =
        *(const uint4*)&g_x16[(size_t)w * 64 + gl * 8];
}
// agg2: warp = 2 nodes; group of 16 lanes owns one node.
__global__ void agg2_kernel() {
    int gt = blockIdx.x * blockDim.x + threadIdx.x;
    int warp = gt >> 5, lane = threadIdx.x & 31;
    int grp = lane >> 4, gl = lane & 15;
    int w = warp * 2 + grp;
    if (w >= N_NODES) return;
    int beg = g_offs[w], end = g_offs[w + 1];
    float inv = 1.0f / (float)max(end - beg, 1);
    float a[8] = {0.f, 0.f, 0.f, 0.f, 0.f, 0.f, 0.f, 0.f};
    int e = beg;
    for (; e + 3 < end; e += 4) {
        int s0 = g_src_sorted[e];
        int s1 = g_src_sorted[e + 1];
        int s2 = g_src_sorted[e + 2];
        int s3 = g_src_sorted[e + 3];
        uint4 p0 = *(const uint4*)&g_A2[(size_t)s0 * 256 + 128 + gl * 8];
        uint4 p1 = *(const uint4*)&g_A2[(size_t)s1 * 256 + 128 + gl * 8];
        uint4 p2 = *(const uint4*)&g_A2[(size_t)s2 * 256 + 128 + gl * 8];
        uint4 p3 = *(const uint4*)&g_A2[(size_t)s3 * 256 + 128 + gl * 8];
        acc8_tree4(p0, p1, p2, p3, a);
    }
    for (; e < end; e++) {
        int ss = g_src_sorted[e];
        uint4 p = *(const uint4*)&g_A2[(size_t)ss * 256 + 128 + gl * 8];
        acc8(p, a);
    }
    uint4 o;
    o.x = pack_h2(a[0] * inv, a[1] * inv);
    o.y = pack_h2(a[2] * inv, a[3] * inv);
    o.z = pack_h2(a[4] * inv, a[5] * inv);
    o.w = pack_h2(a[6] * inv, a[7] * inv);
    *(uint4*)&g_A2[(size_t)w * 256 + gl * 8] = o;
}

// ==================== cp.async pipelined fp16 mma GEMM (BK=32) ====================
template <int KT, bool RELU, int LAYER>
__global__ __launch_bounds__(256) void gemm_fp16_kernel(
    const float* __restrict__ bias, float* __restrict__ out_ext)
{
    constexpr int NCH = KT / 32;
    constexpr int RS = 40;
    constexpr uint32_t ARR_B = 128 * RS * 2;      // 10240 B per array
    constexpr uint32_t STG_B = 2 * ARR_B;         // A + W per stage
    __shared__ __align__(16) __half sbuf[2][2][128 * RS];   // 40 KB

    const __half* A = (LAYER == 1) ? g_A1 : g_A2;
    const __half* W = (LAYER == 1) ? g_w1 : g_w2;

    const int tid = threadIdx.x, lane = tid & 31, wid = tid >> 5;
    const int row0 = blockIdx.x * 128;
    const int valid = min(128, N_NODES - row0);
    const int wr = wid & 3, wc = wid >> 2;

    float c[2][8][4];
#pragma unroll
    for (int mi = 0; mi < 2; mi++)
#pragma unroll
        for (int ni = 0; ni < 8; ni++)
#pragma unroll
            for (int q = 0; q < 4; q++) c[mi][ni][q] = 0.f;

    const uint32_t sb0 = smem_u32(sbuf);

    const int ld_r = tid >> 1;
    const int ld_u = (tid & 1) * 2;
    const int ar = min(row0 + ld_r, N_NODES - 1);
    const size_t goA = (size_t)ar * KT + ld_u * 8;
    const size_t goW = (size_t)ld_r * KT + ld_u * 8;
    const uint32_t dst_ru = (uint32_t)(ld_r * RS + ld_u * 8) * 2;

    const int a_m = ((lane >> 3) & 1) * 8 + (lane & 7);
    const int a_u = (lane >> 4);
    const int b_n = ((lane >> 4) << 3) + (lane & 7);
    const int b_u = ((lane >> 3) & 1);

    {
        uint32_t d = sb0 + dst_ru;
        cp16(d, &A[goA]);            cp16(d + 16, &A[goA + 8]);
        cp16(d + ARR_B, &W[goW]);    cp16(d + ARR_B + 16, &W[goW + 8]);
        CP_COMMIT();
    }

    for (int kc = 0; kc < NCH; kc++) {
        if (kc + 1 < NCH) {
            uint32_t d = sb0 + ((kc + 1) & 1) * STG_B + dst_ru;
            size_t ko = (size_t)(kc + 1) * 32;
            cp16(d, &A[goA + ko]);            cp16(d + 16, &A[goA + ko + 8]);
            cp16(d + ARR_B, &W[goW + ko]);    cp16(d + ARR_B + 16, &W[goW + ko + 8]);
            CP_COMMIT();
            CP_WAIT1();
        } else {
            CP_WAIT0();
        }
        __syncthreads();

        const uint32_t sa = sb0 + (kc & 1) * STG_B;
        const uint32_t sw = sa + ARR_B;

#pragma unroll
        for (int ks = 0; ks < 2; ks++) {
            uint32_t af[2][4], bf[8][2];
#pragma unroll
            for (int mi = 0; mi < 2; mi++) {
                int rr = wr * 32 + mi * 16 + a_m;
                uint32_t off = (uint32_t)(rr * RS + (ks * 2 + a_u) * 8) * 2;
                LDSM_X4(af[mi][0], af[mi][1], af[mi][2], af[mi][3], sa + off);
            }
#pragma unroll
            for (int nj = 0; nj < 4; nj++) {
                int nr = wc * 64 + nj * 16 + b_n;
                uint32_t off = (uint32_t)(nr * RS + (ks * 2 + b_u) * 8) * 2;
                LDSM_X4(bf[nj * 2][0], bf[nj * 2][1], bf[nj * 2 + 1][0], bf[nj * 2 + 1][1], sw + off);
            }
#pragma unroll
            for (int mi = 0; mi < 2; mi++)
#pragma unroll
                for (int ni = 0; ni < 8; ni++)
                    MMA16816F(c[mi][ni], af[mi], bf[ni]);
        }
        __syncthreads();
    }

    // ---- epilogue: bias + (relu); layer1 -> h (fp16) into A2 cols 128..255 ----
    const int g = lane >> 2, tg = lane & 3;
#pragma unroll
    for (int ni = 0; ni < 8; ni++) {
        int col = wc * 64 + ni * 8 + tg * 2;
        float2 bv = *(const float2*)&bias[col];
#pragma unroll
        for (int mi = 0; mi < 2; mi++) {
            int rl = wr * 32 + mi * 16 + g;
#pragma unroll
            for (int hrow = 0; hrow < 2; hrow++) {
                int r = rl + hrow * 8;
                if (r >= valid) continue;
                float v0 = c[mi][ni][hrow * 2 + 0] + bv.x;
                float v1 = c[mi][ni][hrow * 2 + 1] + bv.y;
                if (RELU) { v0 = fmaxf(v0, 0.f); v1 = fmaxf(v1, 0.f); }
                size_t grow = (size_t)(row0 + r);
                if (LAYER == 1) {
                    *(uint32_t*)&g_A2[grow * 256 + 128 + col] = pack_h2(v0, v1);
                } else {
                    float2 o; o.x = v0; o.y = v1;
                    *(float2*)&out_ext[grow * 128 + col] = o;
                }
            }
        }
    }
}

// ==================== entry point ====================
extern "C" void kernel_launch(void* const* d_in, const int* in_sizes, int n_in,
                              void* d_out, int out_size)
{
    (void)n_in; (void)out_size;
    const float* x   = (const float*)d_in[0];
    const void*  ei  = d_in[1];
    const float* W1l = (const float*)d_in[2];
    const float* W1r = (const float*)d_in[3];
    const float* b1  = (const float*)d_in[4];
    const float* W2l = (const float*)d_in[5];
    const float* W2r = (const float*)d_in[6];
    const float* b2  = (const float*)d_in[7];
    float*       out = (float*)d_out;

    int E = in_sizes[1] / 2;
    if (E > E_MAX) E = E_MAX;

    const int agg1_blocks = (((N_NODES + 3) / 4) * 32 + 255) / 256;   // 3125
    const int agg2_blocks = (((N_NODES + 1) / 2) * 32 + 255) / 256;   // 6250
    const int gemm_blocks = (N_NODES + 127) / 128;                    // 782

    init_kernel<<<(E + 255) / 256, 256>>>(ei, (const int*)ei, in_sizes[1], E, x,
                                          W1l, W1r, W2l, W2r);         // 0
    scan_kernel<<<NPART, 1024>>>();                                     // 1
    scatter_kernel<<<(E + 255) / 256, 256>>>(ei, E);                    // 2
    agg1_kernel<<<agg1_blocks, 256>>>();                                // 3 <- profiled
    gemm_fp16_kernel<128, true, 1><<<gemm_blocks, 256>>>(b1, nullptr);  // 4
    agg2_kernel<<<agg2_blocks, 256>>>();                                // 5
    gemm_fp16_kernel<256, false, 2><<<gemm_blocks, 256>>>(b2, out);     // 6
}